// round 10
// baseline (speedup 1.0000x reference)
#include <cuda_runtime.h>

#define EPSF 1.1920929e-07f
typedef unsigned long long ull;

constexpr int TILE  = 64;
constexpr int HALO  = 10;
constexpr int NROWS = 80;          // token rows (5 x m16 tiles)
constexpr int NGATE = 74;          // TILE + HALO
constexpr int NITEM = NGATE * 4;   // 296 (tok,g) items
constexpr int PSTR  = 20;          // u32 stride of packed bf16x2 emb arrays
constexpr int KSTR  = 132;
constexpr int VSTR  = 36;

// shared layout (32-bit word offsets)
constexpr int SM_EHI = 0;                      // [80][20] u32 bf16x2 (emb hi)
constexpr int SM_ELO = SM_EHI + NROWS * PSTR;  // [80][20] u32 (emb lo)
constexpr int SM_K   = SM_ELO + NROWS * PSTR;  // [80][132] f32 keys
constexpr int SM_V   = SM_K + NROWS * KSTR;    // [80][36] f32 values
constexpr int SM_G   = SM_V + NROWS * VSTR;    // [74][4][2] (grr, gate)
constexpr int SM_NN  = SM_G + NGATE * 8;       // [128] n1*n2
constexpr int SM_FLOATS = SM_NN + 128;         // 17360 words = 69440 B

// precomputed weight data (setup kernel -> main kernel)
__device__ unsigned g_wh[320 * 8];   // B-frag hi, lane-exact layout
__device__ unsigned g_wl[320 * 8];   // B-frag lo
__device__ float4   g_bias[320];     // (bias0[0],bias1[0],bias0[1],bias1[1])
__device__ float    g_nn[128];       // n1*n2
__device__ float4   g_cvwf[128];     // cn-folded conv weights

__device__ __forceinline__ ull fma2(ull a, ull b, ull c) {
    ull d; asm("fma.rn.f32x2 %0, %1, %2, %3;" : "=l"(d) : "l"(a), "l"(b), "l"(c)); return d;
}
__device__ __forceinline__ ull mul2(ull a, ull b) {
    ull d; asm("mul.rn.f32x2 %0, %1, %2;" : "=l"(d) : "l"(a), "l"(b)); return d;
}
__device__ __forceinline__ ull add2(ull a, ull b) {
    ull d; asm("add.rn.f32x2 %0, %1, %2;" : "=l"(d) : "l"(a), "l"(b)); return d;
}
__device__ __forceinline__ ull pack2(float x, float y) {
    ull r; asm("mov.b64 %0, {%1, %2};" : "=l"(r) : "f"(x), "f"(y)); return r;
}
__device__ __forceinline__ float lo2(ull a) { float2 f = *(float2*)&a; return f.x; }
__device__ __forceinline__ float hi2(ull a) { float2 f = *(float2*)&a; return f.y; }

__device__ __forceinline__ void split_bf16x2(float x0, float x1,
                                             unsigned& uh, unsigned& ul) {
    unsigned h;
    asm("cvt.rn.bf16x2.f32 %0, %1, %2;" : "=r"(h) : "f"(x1), "f"(x0));
    float h0 = __uint_as_float(h << 16);
    float h1 = __uint_as_float(h & 0xffff0000u);
    float l0 = x0 - h0, l1 = x1 - h1;
    asm("cvt.rn.bf16x2.f32 %0, %1, %2;" : "=r"(ul) : "f"(l1), "f"(l0));
    uh = h;
}

__device__ __forceinline__ void mma16(float* d, unsigned a0, unsigned a1,
                                      unsigned a2, unsigned a3,
                                      unsigned b0, unsigned b1) {
    asm volatile("mma.sync.aligned.m16n8k16.row.col.f32.bf16.bf16.f32 "
                 "{%0,%1,%2,%3}, {%4,%5,%6,%7}, {%8,%9}, {%0,%1,%2,%3};"
                 : "+f"(d[0]), "+f"(d[1]), "+f"(d[2]), "+f"(d[3])
                 : "r"(a0), "r"(a1), "r"(a2), "r"(a3), "r"(b0), "r"(b1));
}

// ---------------- setup kernel: weight prep, runs once per launch ----------
__global__ void engram_setup(const float* __restrict__ Wv, const float* __restrict__ bv,
                             const float* __restrict__ Wk, const float* __restrict__ bk,
                             const float* __restrict__ n1w, const float* __restrict__ n2w,
                             const float* __restrict__ cnw, const float* __restrict__ cvw)
{
    const int tid = threadIdx.x;       // 320 threads
    const int w = tid >> 5, l = tid & 31;
    const int lr = l >> 2, lc = l & 3;
#pragma unroll
    for (int i = 0; i < 8; i++) {
        const int j = i >> 2, kb = (i >> 1) & 1, idx = i & 1;
        const int row = w * 16 + j * 8 + lr;
        const int t   = kb * 8 + lc + idx * 4;   // channel pair (2t, 2t+1)
        const float* src = (row < 128) ? (Wk + row * 32) : (Wv + (row - 128) * 32);
        unsigned h, lo;
        split_bf16x2(src[2 * t], src[2 * t + 1], h, lo);
        g_wh[tid * 8 + i] = h;
        g_wl[tid * 8 + i] = lo;
    }
    {
        const int n0 = w * 16, n1 = w * 16 + 8;
        const float* b0 = (n0 < 128) ? (bk + n0) : (bv + n0 - 128);
        const float* b1 = (n1 < 128) ? (bk + n1) : (bv + n1 - 128);
        g_bias[tid] = make_float4(b0[2 * lc], b0[2 * lc + 1],
                                  b1[2 * lc], b1[2 * lc + 1]);
    }
    if (tid < 128) {
        g_nn[tid] = n1w[tid] * n2w[tid];
        float4 cw = ((const float4*)cvw)[tid];
        float  cn = cnw[tid];
        g_cvwf[tid] = make_float4(cw.x * cn, cw.y * cn, cw.z * cn, cw.w * cn);
    }
}

// ---------------- main kernel ----------------------------------------------
__global__ void __launch_bounds__(320, 3)
engram_kernel(const float* __restrict__ emb, const float* __restrict__ hid,
              float* __restrict__ out, int T)
{
    extern __shared__ float sm[];
    unsigned* ehi = (unsigned*)(sm + SM_EHI);
    unsigned* elo = (unsigned*)(sm + SM_ELO);

    const int tid        = threadIdx.x;
    const int b          = blockIdx.y;
    const int tile_start = blockIdx.x * TILE;
    const long base_tok  = (long)b * T + tile_start;
    const float* hbase   = hid + (base_tok - HALO) * 128;

    // ---- B fragments + bias: coalesced LDG from precomputed globals ----
    uint4 H0 = ((const uint4*)g_wh)[tid * 2];
    uint4 H1 = ((const uint4*)g_wh)[tid * 2 + 1];
    uint4 L0 = ((const uint4*)g_wl)[tid * 2];
    uint4 L1 = ((const uint4*)g_wl)[tid * 2 + 1];
    float4 bf = g_bias[tid];

    // ---- stage emb (hi/lo bf16x2) + nn ----
    for (int i4 = tid; i4 < NROWS * 8; i4 += 320) {
        int tok = i4 >> 3, q = i4 & 7;
        int gt  = tile_start - HALO + tok;
        float4 val = make_float4(0.f, 0.f, 0.f, 0.f);
        if (tok < NGATE && gt >= 0)
            val = ((const float4*)emb)[(base_tok - HALO + tok) * 8 + q];
        unsigned h0, l0, h1, l1;
        split_bf16x2(val.x, val.y, h0, l0);
        split_bf16x2(val.z, val.w, h1, l1);
        const int base = tok * PSTR + 2 * q;
        ehi[base] = h0; ehi[base + 1] = h1;
        elo[base] = l0; elo[base + 1] = l1;
    }
    if (tid < 32) {
        float4 nn4 = ((const float4*)g_nn)[tid];
        *(float4*)(sm + SM_NN + tid * 4) = nn4;
    }
    __syncthreads();

    const int w  = tid >> 5, l = tid & 31;
    const int lr = l >> 2, lc = l & 3;

    // ---- Phase A: 3-term bf16 mma, interleaved d0/d1 chains ----
#pragma unroll 1
    for (int m = 0; m < 5; m++) {
        const int t0 = m * 16;
        float d0[4], d1[4];
        d0[0] = bf.x; d0[1] = bf.y; d0[2] = bf.x; d0[3] = bf.y;
        d1[0] = bf.z; d1[1] = bf.w; d1[2] = bf.z; d1[3] = bf.w;
#pragma unroll
        for (int kb = 0; kb < 2; kb++) {
            const int base = (t0 + lr) * PSTR + kb * 8 + lc;
            unsigned a0 = ehi[base],     a1 = ehi[base + 8 * PSTR];
            unsigned a2 = ehi[base + 4], a3 = ehi[base + 8 * PSTR + 4];
            unsigned q0 = elo[base],     q1 = elo[base + 8 * PSTR];
            unsigned q2 = elo[base + 4], q3 = elo[base + 8 * PSTR + 4];
            const unsigned bh00 = kb ? H0.z : H0.x, bh01 = kb ? H0.w : H0.y;
            const unsigned bh10 = kb ? H1.z : H1.x, bh11 = kb ? H1.w : H1.y;
            const unsigned bl00 = kb ? L0.z : L0.x, bl01 = kb ? L0.w : L0.y;
            const unsigned bl10 = kb ? L1.z : L1.x, bl11 = kb ? L1.w : L1.y;
            mma16(d0, q0, q1, q2, q3, bh00, bh01);   // Al*Bh
            mma16(d1, q0, q1, q2, q3, bh10, bh11);
            mma16(d0, a0, a1, a2, a3, bl00, bl01);   // Ah*Bl
            mma16(d1, a0, a1, a2, a3, bl10, bl11);
            mma16(d0, a0, a1, a2, a3, bh00, bh01);   // Ah*Bh
            mma16(d1, a0, a1, a2, a3, bh10, bh11);
        }
        const int n0a = w * 16;
        if (n0a < 128) {    // warp-uniform: warps 0-7 key channels
            float* kd = sm + SM_K + n0a + 2 * lc;
            *(float2*)(kd + (t0 + lr) * KSTR)         = make_float2(d0[0], d0[1]);
            *(float2*)(kd + (t0 + lr + 8) * KSTR)     = make_float2(d0[2], d0[3]);
            *(float2*)(kd + 8 + (t0 + lr) * KSTR)     = make_float2(d1[0], d1[1]);
            *(float2*)(kd + 8 + (t0 + lr + 8) * KSTR) = make_float2(d1[2], d1[3]);
        } else {            // warps 8,9: value channels
            float* vd = sm + SM_V + (n0a - 128) + 2 * lc;
            *(float2*)(vd + (t0 + lr) * VSTR)         = make_float2(d0[0], d0[1]);
            *(float2*)(vd + (t0 + lr + 8) * VSTR)     = make_float2(d0[2], d0[3]);
            *(float2*)(vd + 8 + (t0 + lr) * VSTR)     = make_float2(d1[0], d1[1]);
            *(float2*)(vd + 8 + (t0 + lr + 8) * VSTR) = make_float2(d1[2], d1[3]);
        }
    }
    __syncthreads();

    // ---- Phase B: 8-lane groups; coalesced hid LDG (1 inst / 4 rows) ----
    {
        const int sub = l >> 3;
        const int lc8 = l & 7;
#pragma unroll 1
        for (int r0 = w * 4; r0 < NITEM; r0 += 40) {
            const int r   = r0 + sub;
            const int tok = r >> 2, g = r & 3;
            const bool valid = (r < NITEM) && (tile_start - HALO + tok >= 0);

            float4 h4 = make_float4(0.f, 0.f, 0.f, 0.f);
            if (valid) h4 = ((const float4*)hbase)[r * 8 + lc8];

            const int c = lc8 * 4;
            ulonglong2 k2 = *(const ulonglong2*)(sm + SM_K + tok * KSTR + g * 32 + c);
            ulonglong2 n2 = *(const ulonglong2*)(sm + SM_NN + g * 32 + c);
            ulonglong2 v2 = *(const ulonglong2*)(sm + SM_V + tok * VSTR + c);
            ull hx = pack2(h4.x, h4.y), hy = pack2(h4.z, h4.w);

            ull skk2 = fma2(k2.y, k2.y, mul2(k2.x, k2.x));
            ull shh2 = fma2(hy, hy, mul2(hx, hx));
            ull skh2 = fma2(mul2(k2.y, hy), n2.y, mul2(mul2(k2.x, hx), n2.x));
            ull svv2 = fma2(v2.y, v2.y, mul2(v2.x, v2.x));

            ull s1 = pack2(lo2(skk2) + hi2(skk2), lo2(shh2) + hi2(shh2));
            ull s2 = pack2(lo2(skh2) + hi2(skh2), lo2(svv2) + hi2(svv2));
#pragma unroll
            for (int off = 1; off < 8; off <<= 1) {
                s1 = add2(s1, __shfl_xor_sync(0xffffffffu, s1, off));
                s2 = add2(s2, __shfl_xor_sync(0xffffffffu, s2, off));
            }
            if (lc8 == 0) {
                float grr = 0.f, gate = 0.f;
                if (valid) {
                    const float skk = lo2(s1), shh = hi2(s1);
                    const float skh = lo2(s2), svv = hi2(s2);
                    const float rs1 = rsqrtf(skk * (1.f/32.f) + EPSF);
                    const float rs2 = rsqrtf(shh * (1.f/32.f) + EPSF);
                    const float dot = skh * rs1 * rs2 * 0.17677669529663687f;
                    const float sq  = sqrtf(fmaxf(fabsf(dot), 1e-6f));
                    const float gs  = (dot > 0.f) ? sq : ((dot < 0.f) ? -sq : 0.f);
                    gate = 1.f / (1.f + __expf(-gs));
                    grr  = gate * rsqrtf(gate * gate * svv * (1.f/32.f) + EPSF);
                }
                if (r < NITEM) {
                    sm[SM_G + tok * 8 + g * 2 + 0] = grr;
                    sm[SM_G + tok * 8 + g * 2 + 1] = gate;
                }
            }
        }
    }
    __syncthreads();

    // ---- Phase C: conv + SiLU + residual (cn pre-folded) ----
    {
        const int g    = l >> 3;
        const int c0   = (l & 7) * 4;
        const int chb  = g * 32 + c0;
        float4 cw0 = g_cvwf[chb + 0];
        float4 cw1 = g_cvwf[chb + 1];
        float4 cw2 = g_cvwf[chb + 2];
        float4 cw3 = g_cvwf[chb + 3];
        ull t9a = pack2(cw0.x, cw1.x), t9b = pack2(cw2.x, cw3.x);
        ull t6a = pack2(cw0.y, cw1.y), t6b = pack2(cw2.y, cw3.y);
        ull t3a = pack2(cw0.z, cw1.z), t3b = pack2(cw2.z, cw3.z);
        ull t0a = pack2(cw0.w, cw1.w), t0b = pack2(cw2.w, cw3.w);

        for (int mt = w; mt < TILE; mt += 10) {
            const int tok = mt + HALO;
            const float* gp = sm + SM_G;
            const float grr9 = gp[(tok-9)*8 + g*2], grr6 = gp[(tok-6)*8 + g*2];
            const float grr3 = gp[(tok-3)*8 + g*2], grr0 = gp[(tok  )*8 + g*2];
            const float gate = gp[tok*8 + g*2 + 1];
            const ulonglong2 v9 = *(const ulonglong2*)&sm[SM_V + (tok-9)*VSTR + c0];
            const ulonglong2 v6 = *(const ulonglong2*)&sm[SM_V + (tok-6)*VSTR + c0];
            const ulonglong2 v3 = *(const ulonglong2*)&sm[SM_V + (tok-3)*VSTR + c0];
            const ulonglong2 v0 = *(const ulonglong2*)&sm[SM_V + (tok  )*VSTR + c0];
            const ull g92 = pack2(grr9, grr9), g62 = pack2(grr6, grr6);
            const ull g32 = pack2(grr3, grr3), g02 = pack2(grr0, grr0);
            ull ya = mul2(mul2(t9a, v9.x), g92);
            ull yb = mul2(mul2(t9b, v9.y), g92);
            ya = fma2(mul2(t6a, v6.x), g62, ya);
            yb = fma2(mul2(t6b, v6.y), g62, yb);
            ya = fma2(mul2(t3a, v3.x), g32, ya);
            yb = fma2(mul2(t3b, v3.y), g32, yb);
            ya = fma2(mul2(t0a, v0.x), g02, ya);
            yb = fma2(mul2(t0b, v0.y), g02, yb);
            const float y0 = lo2(ya), y1 = hi2(ya), y2 = lo2(yb), y3 = hi2(yb);
            const float s0 = y0 / (1.f + __expf(-y0));
            const float s1 = y1 / (1.f + __expf(-y1));
            const float s2 = y2 / (1.f + __expf(-y2));
            const float s3 = y3 / (1.f + __expf(-y3));
            float4 o;
            o.x = fmaf(gate, lo2(v0.x), s0);
            o.y = fmaf(gate, hi2(v0.x), s1);
            o.z = fmaf(gate, lo2(v0.y), s2);
            o.w = fmaf(gate, hi2(v0.y), s3);
            ((float4*)out)[(((base_tok + mt) * 4 + g) * 32 + c0) >> 2] = o;
        }
    }
}

extern "C" void kernel_launch(void* const* d_in, const int* in_sizes, int n_in,
                              void* d_out, int out_size)
{
    const float* emb = (const float*)d_in[0];
    const float* hid = (const float*)d_in[1];
    const float* Wv  = (const float*)d_in[2];
    const float* bv  = (const float*)d_in[3];
    const float* Wk  = (const float*)d_in[4];
    const float* bk  = (const float*)d_in[5];
    const float* n1w = (const float*)d_in[6];
    const float* n2w = (const float*)d_in[7];
    const float* cnw = (const float*)d_in[8];
    const float* cvw = (const float*)d_in[9];
    float* out = (float*)d_out;

    const int T = 8192;
    const int B = in_sizes[0] / (T * 32);
    const size_t smem = SM_FLOATS * sizeof(float);   // 69440 B

    cudaFuncSetAttribute(engram_kernel,
                         cudaFuncAttributeMaxDynamicSharedMemorySize, (int)smem);

    engram_setup<<<1, 320>>>(Wv, bv, Wk, bk, n1w, n2w, cnw, cvw);

    dim3 grid(T / TILE, B);
    engram_kernel<<<grid, 320, smem>>>(emb, hid, out, T);
}

// round 11
// speedup vs baseline: 1.0500x; 1.0500x over previous
#include <cuda_runtime.h>

#define EPSF 1.1920929e-07f
typedef unsigned long long ull;

constexpr int TILE  = 64;
constexpr int HALO  = 10;
constexpr int NROWS = 80;          // token rows (5 x m16 tiles)
constexpr int NGATE = 74;          // TILE + HALO
constexpr int NITEM = NGATE * 4;   // 296 (tok,g) items
constexpr int PSTR  = 20;          // u32 stride of packed bf16x2 emb arrays
constexpr int KSTR  = 132;
constexpr int VSTR  = 36;

// shared layout (32-bit word offsets)
constexpr int SM_EHI = 0;                      // [80][20] u32 bf16x2 (emb hi)
constexpr int SM_ELO = SM_EHI + NROWS * PSTR;  // [80][20] u32 (emb lo)
constexpr int SM_K   = SM_ELO + NROWS * PSTR;  // [80][132] f32 keys
constexpr int SM_V   = SM_K + NROWS * KSTR;    // [80][36] f32 values
constexpr int SM_G   = SM_V + NROWS * VSTR;    // [74][4][2] (grr, gate)
constexpr int SM_NN  = SM_G + NGATE * 8;       // [128] n1*n2
constexpr int SM_FLOATS = SM_NN + 128;         // 17360 words = 69440 B

__device__ __forceinline__ ull fma2(ull a, ull b, ull c) {
    ull d; asm("fma.rn.f32x2 %0, %1, %2, %3;" : "=l"(d) : "l"(a), "l"(b), "l"(c)); return d;
}
__device__ __forceinline__ ull mul2(ull a, ull b) {
    ull d; asm("mul.rn.f32x2 %0, %1, %2;" : "=l"(d) : "l"(a), "l"(b)); return d;
}
__device__ __forceinline__ ull add2(ull a, ull b) {
    ull d; asm("add.rn.f32x2 %0, %1, %2;" : "=l"(d) : "l"(a), "l"(b)); return d;
}
__device__ __forceinline__ ull pack2(float x, float y) {
    ull r; asm("mov.b64 %0, {%1, %2};" : "=l"(r) : "f"(x), "f"(y)); return r;
}
__device__ __forceinline__ float lo2(ull a) { float2 f = *(float2*)&a; return f.x; }
__device__ __forceinline__ float hi2(ull a) { float2 f = *(float2*)&a; return f.y; }

__device__ __forceinline__ void split_bf16x2(float x0, float x1,
                                             unsigned& uh, unsigned& ul) {
    unsigned h;
    asm("cvt.rn.bf16x2.f32 %0, %1, %2;" : "=r"(h) : "f"(x1), "f"(x0));
    float h0 = __uint_as_float(h << 16);
    float h1 = __uint_as_float(h & 0xffff0000u);
    float l0 = x0 - h0, l1 = x1 - h1;
    asm("cvt.rn.bf16x2.f32 %0, %1, %2;" : "=r"(ul) : "f"(l1), "f"(l0));
    uh = h;
}

__device__ __forceinline__ void mma16(float* d, unsigned a0, unsigned a1,
                                      unsigned a2, unsigned a3,
                                      unsigned b0, unsigned b1) {
    asm volatile("mma.sync.aligned.m16n8k16.row.col.f32.bf16.bf16.f32 "
                 "{%0,%1,%2,%3}, {%4,%5,%6,%7}, {%8,%9}, {%0,%1,%2,%3};"
                 : "+f"(d[0]), "+f"(d[1]), "+f"(d[2]), "+f"(d[3])
                 : "r"(a0), "r"(a1), "r"(a2), "r"(a3), "r"(b0), "r"(b1));
}

__global__ void __launch_bounds__(320, 3)
engram_kernel(const float* __restrict__ emb, const float* __restrict__ hid,
              const float* __restrict__ Wv,  const float* __restrict__ bv,
              const float* __restrict__ Wk,  const float* __restrict__ bk,
              const float* __restrict__ n1w, const float* __restrict__ n2w,
              const float* __restrict__ cnw, const float* __restrict__ cvw,
              float* __restrict__ out, int T)
{
    extern __shared__ float sm[];
    unsigned* ehi = (unsigned*)(sm + SM_EHI);
    unsigned* elo = (unsigned*)(sm + SM_ELO);

    const int tid        = threadIdx.x;
    const int b          = blockIdx.y;
    const int tile_start = blockIdx.x * TILE;
    const long base_tok  = (long)b * T + tile_start;
    const float* hbase   = hid + (base_tok - HALO) * 128;

    const int w  = tid >> 5, l = tid & 31;
    const int lr = l >> 2, lc = l & 3;

    // ---- per-thread B fragments + bias, computed straight from weights ----
    // (independent LDG.64s issued in the prologue; overlap emb staging below)
    unsigned H[8], L[8];
#pragma unroll
    for (int i = 0; i < 8; i++) {
        const int j = i >> 2, kb = (i >> 1) & 1, idx = i & 1;
        const int row = w * 16 + j * 8 + lr;
        const int t   = kb * 8 + lc + idx * 4;      // channel pair (2t, 2t+1)
        const float* src = (row < 128) ? (Wk + row * 32) : (Wv + (row - 128) * 32);
        float2 p = *(const float2*)(src + 2 * t);
        split_bf16x2(p.x, p.y, H[i], L[i]);
    }
    float4 bf;
    {
        const int n0 = w * 16, n1 = w * 16 + 8;
        const float* b0 = (n0 < 128) ? (bk + n0) : (bv + n0 - 128);
        const float* b1 = (n1 < 128) ? (bk + n1) : (bv + n1 - 128);
        bf = make_float4(b0[2 * lc], b0[2 * lc + 1], b1[2 * lc], b1[2 * lc + 1]);
    }

    // ---- stage emb (hi/lo bf16x2) + nn ----
    for (int i4 = tid; i4 < NROWS * 8; i4 += 320) {
        int tok = i4 >> 3, q = i4 & 7;
        int gt  = tile_start - HALO + tok;
        float4 val = make_float4(0.f, 0.f, 0.f, 0.f);
        if (tok < NGATE && gt >= 0)
            val = ((const float4*)emb)[(base_tok - HALO + tok) * 8 + q];
        unsigned h0, l0, h1, l1;
        split_bf16x2(val.x, val.y, h0, l0);
        split_bf16x2(val.z, val.w, h1, l1);
        const int base = tok * PSTR + 2 * q;
        ehi[base] = h0; ehi[base + 1] = h1;
        elo[base] = l0; elo[base + 1] = l1;
    }
    if (tid < 128) sm[SM_NN + tid] = n1w[tid] * n2w[tid];
    __syncthreads();

    // ---- Phase A: 3-term bf16 mma, interleaved d0/d1 chains ----
#pragma unroll 1
    for (int m = 0; m < 5; m++) {
        const int t0 = m * 16;
        float d0[4], d1[4];
        d0[0] = bf.x; d0[1] = bf.y; d0[2] = bf.x; d0[3] = bf.y;
        d1[0] = bf.z; d1[1] = bf.w; d1[2] = bf.z; d1[3] = bf.w;
#pragma unroll
        for (int kb = 0; kb < 2; kb++) {
            const int base = (t0 + lr) * PSTR + kb * 8 + lc;
            unsigned a0 = ehi[base],     a1 = ehi[base + 8 * PSTR];
            unsigned a2 = ehi[base + 4], a3 = ehi[base + 8 * PSTR + 4];
            unsigned q0 = elo[base],     q1 = elo[base + 8 * PSTR];
            unsigned q2 = elo[base + 4], q3 = elo[base + 8 * PSTR + 4];
            mma16(d0, q0, q1, q2, q3, H[kb*2],   H[kb*2+1]);     // Al*Bh
            mma16(d1, q0, q1, q2, q3, H[4+kb*2], H[4+kb*2+1]);
            mma16(d0, a0, a1, a2, a3, L[kb*2],   L[kb*2+1]);     // Ah*Bl
            mma16(d1, a0, a1, a2, a3, L[4+kb*2], L[4+kb*2+1]);
            mma16(d0, a0, a1, a2, a3, H[kb*2],   H[kb*2+1]);     // Ah*Bh
            mma16(d1, a0, a1, a2, a3, H[4+kb*2], H[4+kb*2+1]);
        }
        const int n0a = w * 16;
        if (n0a < 128) {    // warp-uniform: warps 0-7 key channels
            float* kd = sm + SM_K + n0a + 2 * lc;
            *(float2*)(kd + (t0 + lr) * KSTR)         = make_float2(d0[0], d0[1]);
            *(float2*)(kd + (t0 + lr + 8) * KSTR)     = make_float2(d0[2], d0[3]);
            *(float2*)(kd + 8 + (t0 + lr) * KSTR)     = make_float2(d1[0], d1[1]);
            *(float2*)(kd + 8 + (t0 + lr + 8) * KSTR) = make_float2(d1[2], d1[3]);
        } else {            // warps 8,9: value channels
            float* vd = sm + SM_V + (n0a - 128) + 2 * lc;
            *(float2*)(vd + (t0 + lr) * VSTR)         = make_float2(d0[0], d0[1]);
            *(float2*)(vd + (t0 + lr + 8) * VSTR)     = make_float2(d0[2], d0[3]);
            *(float2*)(vd + 8 + (t0 + lr) * VSTR)     = make_float2(d1[0], d1[1]);
            *(float2*)(vd + 8 + (t0 + lr + 8) * VSTR) = make_float2(d1[2], d1[3]);
        }
    }
    __syncthreads();

    // ---- Phase B: 8-lane groups; coalesced hid LDG (1 inst / 4 rows) ----
    {
        const int sub = l >> 3;
        const int lc8 = l & 7;
#pragma unroll 1
        for (int r0 = w * 4; r0 < NITEM; r0 += 40) {
            const int r   = r0 + sub;
            const int tok = r >> 2, g = r & 3;
            const bool valid = (r < NITEM) && (tile_start - HALO + tok >= 0);

            float4 h4 = make_float4(0.f, 0.f, 0.f, 0.f);
            if (valid) h4 = ((const float4*)hbase)[r * 8 + lc8];

            const int c = lc8 * 4;
            ulonglong2 k2 = *(const ulonglong2*)(sm + SM_K + tok * KSTR + g * 32 + c);
            ulonglong2 n2 = *(const ulonglong2*)(sm + SM_NN + g * 32 + c);
            ulonglong2 v2 = *(const ulonglong2*)(sm + SM_V + tok * VSTR + c);
            ull hx = pack2(h4.x, h4.y), hy = pack2(h4.z, h4.w);

            ull skk2 = fma2(k2.y, k2.y, mul2(k2.x, k2.x));
            ull shh2 = fma2(hy, hy, mul2(hx, hx));
            ull skh2 = fma2(mul2(k2.y, hy), n2.y, mul2(mul2(k2.x, hx), n2.x));
            ull svv2 = fma2(v2.y, v2.y, mul2(v2.x, v2.x));

            ull s1 = pack2(lo2(skk2) + hi2(skk2), lo2(shh2) + hi2(shh2));
            ull s2 = pack2(lo2(skh2) + hi2(skh2), lo2(svv2) + hi2(svv2));
#pragma unroll
            for (int off = 1; off < 8; off <<= 1) {
                s1 = add2(s1, __shfl_xor_sync(0xffffffffu, s1, off));
                s2 = add2(s2, __shfl_xor_sync(0xffffffffu, s2, off));
            }
            if (lc8 == 0) {
                float grr = 0.f, gate = 0.f;
                if (valid) {
                    const float skk = lo2(s1), shh = hi2(s1);
                    const float skh = lo2(s2), svv = hi2(s2);
                    const float rs1 = rsqrtf(skk * (1.f/32.f) + EPSF);
                    const float rs2 = rsqrtf(shh * (1.f/32.f) + EPSF);
                    const float dot = skh * rs1 * rs2 * 0.17677669529663687f;
                    const float sq  = sqrtf(fmaxf(fabsf(dot), 1e-6f));
                    const float gs  = (dot > 0.f) ? sq : ((dot < 0.f) ? -sq : 0.f);
                    gate = 1.f / (1.f + __expf(-gs));
                    grr  = gate * rsqrtf(gate * gate * svv * (1.f/32.f) + EPSF);
                }
                if (r < NITEM) {
                    sm[SM_G + tok * 8 + g * 2 + 0] = grr;
                    sm[SM_G + tok * 8 + g * 2 + 1] = gate;
                }
            }
        }
    }
    __syncthreads();

    // ---- Phase C: conv + SiLU + residual ----
    {
        const int g    = l >> 3;
        const int c0   = (l & 7) * 4;
        const int chb  = g * 32 + c0;
        float4 cw0 = ((const float4*)cvw)[chb + 0];
        float4 cw1 = ((const float4*)cvw)[chb + 1];
        float4 cw2 = ((const float4*)cvw)[chb + 2];
        float4 cw3 = ((const float4*)cvw)[chb + 3];
        ull t9a = pack2(cw0.x, cw1.x), t9b = pack2(cw2.x, cw3.x);
        ull t6a = pack2(cw0.y, cw1.y), t6b = pack2(cw2.y, cw3.y);
        ull t3a = pack2(cw0.z, cw1.z), t3b = pack2(cw2.z, cw3.z);
        ull t0a = pack2(cw0.w, cw1.w), t0b = pack2(cw2.w, cw3.w);
        ull cna = pack2(cnw[chb], cnw[chb+1]), cnb = pack2(cnw[chb+2], cnw[chb+3]);

        for (int mt = w; mt < TILE; mt += 10) {
            const int tok = mt + HALO;
            const float* gp = sm + SM_G;
            const float grr9 = gp[(tok-9)*8 + g*2], grr6 = gp[(tok-6)*8 + g*2];
            const float grr3 = gp[(tok-3)*8 + g*2], grr0 = gp[(tok  )*8 + g*2];
            const float gate = gp[tok*8 + g*2 + 1];
            const ulonglong2 v9 = *(const ulonglong2*)&sm[SM_V + (tok-9)*VSTR + c0];
            const ulonglong2 v6 = *(const ulonglong2*)&sm[SM_V + (tok-6)*VSTR + c0];
            const ulonglong2 v3 = *(const ulonglong2*)&sm[SM_V + (tok-3)*VSTR + c0];
            const ulonglong2 v0 = *(const ulonglong2*)&sm[SM_V + (tok  )*VSTR + c0];
            const ull g92 = pack2(grr9, grr9), g62 = pack2(grr6, grr6);
            const ull g32 = pack2(grr3, grr3), g02 = pack2(grr0, grr0);
            ull ya = mul2(mul2(t9a, v9.x), g92);
            ull yb = mul2(mul2(t9b, v9.y), g92);
            ya = fma2(mul2(t6a, v6.x), g62, ya);
            yb = fma2(mul2(t6b, v6.y), g62, yb);
            ya = fma2(mul2(t3a, v3.x), g32, ya);
            yb = fma2(mul2(t3b, v3.y), g32, yb);
            ya = fma2(mul2(t0a, v0.x), g02, ya);
            yb = fma2(mul2(t0b, v0.y), g02, yb);
            ya = mul2(ya, cna);
            yb = mul2(yb, cnb);
            const float y0 = lo2(ya), y1 = hi2(ya), y2 = lo2(yb), y3 = hi2(yb);
            const float s0 = y0 / (1.f + __expf(-y0));
            const float s1 = y1 / (1.f + __expf(-y1));
            const float s2 = y2 / (1.f + __expf(-y2));
            const float s3 = y3 / (1.f + __expf(-y3));
            float4 o;
            o.x = fmaf(gate, lo2(v0.x), s0);
            o.y = fmaf(gate, hi2(v0.x), s1);
            o.z = fmaf(gate, lo2(v0.y), s2);
            o.w = fmaf(gate, hi2(v0.y), s3);
            ((float4*)out)[(((base_tok + mt) * 4 + g) * 32 + c0) >> 2] = o;
        }
    }
}

extern "C" void kernel_launch(void* const* d_in, const int* in_sizes, int n_in,
                              void* d_out, int out_size)
{
    const float* emb = (const float*)d_in[0];
    const float* hid = (const float*)d_in[1];
    const float* Wv  = (const float*)d_in[2];
    const float* bv  = (const float*)d_in[3];
    const float* Wk  = (const float*)d_in[4];
    const float* bk  = (const float*)d_in[5];
    const float* n1w = (const float*)d_in[6];
    const float* n2w = (const float*)d_in[7];
    const float* cnw = (const float*)d_in[8];
    const float* cvw = (const float*)d_in[9];
    float* out = (float*)d_out;

    const int T = 8192;
    const int B = in_sizes[0] / (T * 32);
    const size_t smem = SM_FLOATS * sizeof(float);   // 69440 B

    cudaFuncSetAttribute(engram_kernel,
                         cudaFuncAttributeMaxDynamicSharedMemorySize, (int)smem);

    dim3 grid(T / TILE, B);
    engram_kernel<<<grid, 320, smem>>>(emb, hid, Wv, bv, Wk, bk,
                                       n1w, n2w, cnw, cvw, out, T);
}

// round 12
// speedup vs baseline: 1.1002x; 1.0479x over previous
#include <cuda_runtime.h>

#define EPSF 1.1920929e-07f
typedef unsigned long long ull;

constexpr int TILE  = 64;
constexpr int HALO  = 10;
constexpr int NROWS = 80;          // token rows (5 x m16 tiles)
constexpr int NGATE = 74;          // TILE + HALO
constexpr int NITEM = NGATE * 4;   // 296 (tok,g) items
constexpr int PSTR  = 20;          // u32 stride of packed bf16x2 emb arrays
constexpr int KSTR  = 132;
constexpr int VSTR  = 36;

// shared layout (32-bit word offsets)
constexpr int SM_EHI = 0;                      // [80][20] u32 bf16x2 (emb hi)
constexpr int SM_ELO = SM_EHI + NROWS * PSTR;  // [80][20] u32 (emb lo)
constexpr int SM_K   = SM_ELO + NROWS * PSTR;  // [80][132] f32 keys
constexpr int SM_V   = SM_K + NROWS * KSTR;    // [80][36] f32 values
constexpr int SM_G   = SM_V + NROWS * VSTR;    // [74][4][2] (grr, gate)
constexpr int SM_NN  = SM_G + NGATE * 8;       // [128] n1*n2
constexpr int SM_FLOATS = SM_NN + 128;         // 17360 words = 69440 B

__device__ __forceinline__ ull fma2(ull a, ull b, ull c) {
    ull d; asm("fma.rn.f32x2 %0, %1, %2, %3;" : "=l"(d) : "l"(a), "l"(b), "l"(c)); return d;
}
__device__ __forceinline__ ull mul2(ull a, ull b) {
    ull d; asm("mul.rn.f32x2 %0, %1, %2;" : "=l"(d) : "l"(a), "l"(b)); return d;
}
__device__ __forceinline__ ull add2(ull a, ull b) {
    ull d; asm("add.rn.f32x2 %0, %1, %2;" : "=l"(d) : "l"(a), "l"(b)); return d;
}
__device__ __forceinline__ ull pack2(float x, float y) {
    ull r; asm("mov.b64 %0, {%1, %2};" : "=l"(r) : "f"(x), "f"(y)); return r;
}
__device__ __forceinline__ float lo2(ull a) { float2 f = *(float2*)&a; return f.x; }
__device__ __forceinline__ float hi2(ull a) { float2 f = *(float2*)&a; return f.y; }
__device__ __forceinline__ float frcp(float x) {
    float r; asm("rcp.approx.f32 %0, %1;" : "=f"(r) : "f"(x)); return r;
}
__device__ __forceinline__ float fsqrta(float x) {
    float r; asm("sqrt.approx.f32 %0, %1;" : "=f"(r) : "f"(x)); return r;
}

__device__ __forceinline__ void split_bf16x2(float x0, float x1,
                                             unsigned& uh, unsigned& ul) {
    unsigned h;
    asm("cvt.rn.bf16x2.f32 %0, %1, %2;" : "=r"(h) : "f"(x1), "f"(x0));
    float h0 = __uint_as_float(h << 16);
    float h1 = __uint_as_float(h & 0xffff0000u);
    float l0 = x0 - h0, l1 = x1 - h1;
    asm("cvt.rn.bf16x2.f32 %0, %1, %2;" : "=r"(ul) : "f"(l1), "f"(l0));
    uh = h;
}

__device__ __forceinline__ void mma16(float* d, unsigned a0, unsigned a1,
                                      unsigned a2, unsigned a3,
                                      unsigned b0, unsigned b1) {
    asm volatile("mma.sync.aligned.m16n8k16.row.col.f32.bf16.bf16.f32 "
                 "{%0,%1,%2,%3}, {%4,%5,%6,%7}, {%8,%9}, {%0,%1,%2,%3};"
                 : "+f"(d[0]), "+f"(d[1]), "+f"(d[2]), "+f"(d[3])
                 : "r"(a0), "r"(a1), "r"(a2), "r"(a3), "r"(b0), "r"(b1));
}

__global__ void __launch_bounds__(320, 3)
engram_kernel(const float* __restrict__ emb, const float* __restrict__ hid,
              const float* __restrict__ Wv,  const float* __restrict__ bv,
              const float* __restrict__ Wk,  const float* __restrict__ bk,
              const float* __restrict__ n1w, const float* __restrict__ n2w,
              const float* __restrict__ cnw, const float* __restrict__ cvw,
              float* __restrict__ out, int T)
{
    extern __shared__ float sm[];
    unsigned* ehi = (unsigned*)(sm + SM_EHI);
    unsigned* elo = (unsigned*)(sm + SM_ELO);

    const int tid        = threadIdx.x;
    const int b          = blockIdx.y;
    const int tile_start = blockIdx.x * TILE;
    const long base_tok  = (long)b * T + tile_start;
    const float* hbase   = hid + (base_tok - HALO) * 128;

    const int w  = tid >> 5, l = tid & 31;
    const int lr = l >> 2, lc = l & 3;

    // ---- per-thread B fragments + bias, computed straight from weights ----
    unsigned H[8], L[8];
#pragma unroll
    for (int i = 0; i < 8; i++) {
        const int j = i >> 2, kb = (i >> 1) & 1, idx = i & 1;
        const int row = w * 16 + j * 8 + lr;
        const int t   = kb * 8 + lc + idx * 4;      // channel pair (2t, 2t+1)
        const float* src = (row < 128) ? (Wk + row * 32) : (Wv + (row - 128) * 32);
        float2 p = *(const float2*)(src + 2 * t);
        split_bf16x2(p.x, p.y, H[i], L[i]);
    }
    float4 bf;
    {
        const int n0 = w * 16, n1 = w * 16 + 8;
        const float* b0 = (n0 < 128) ? (bk + n0) : (bv + n0 - 128);
        const float* b1 = (n1 < 128) ? (bk + n1) : (bv + n1 - 128);
        bf = make_float4(b0[2 * lc], b0[2 * lc + 1], b1[2 * lc], b1[2 * lc + 1]);
    }

    // ---- stage emb (hi/lo bf16x2) + nn ----
    for (int i4 = tid; i4 < NROWS * 8; i4 += 320) {
        int tok = i4 >> 3, q = i4 & 7;
        int gt  = tile_start - HALO + tok;
        float4 val = make_float4(0.f, 0.f, 0.f, 0.f);
        if (tok < NGATE && gt >= 0)
            val = ((const float4*)emb)[(base_tok - HALO + tok) * 8 + q];
        unsigned h0, l0, h1, l1;
        split_bf16x2(val.x, val.y, h0, l0);
        split_bf16x2(val.z, val.w, h1, l1);
        const int base = tok * PSTR + 2 * q;
        ehi[base] = h0; ehi[base + 1] = h1;
        elo[base] = l0; elo[base + 1] = l1;
    }
    if (tid < 128) sm[SM_NN + tid] = n1w[tid] * n2w[tid];
    __syncthreads();

    // ---- Phase A: 3-term bf16 mma, interleaved d0/d1 chains ----
#pragma unroll 1
    for (int m = 0; m < 5; m++) {
        const int t0 = m * 16;
        float d0[4], d1[4];
        d0[0] = bf.x; d0[1] = bf.y; d0[2] = bf.x; d0[3] = bf.y;
        d1[0] = bf.z; d1[1] = bf.w; d1[2] = bf.z; d1[3] = bf.w;
#pragma unroll
        for (int kb = 0; kb < 2; kb++) {
            const int base = (t0 + lr) * PSTR + kb * 8 + lc;
            unsigned a0 = ehi[base],     a1 = ehi[base + 8 * PSTR];
            unsigned a2 = ehi[base + 4], a3 = ehi[base + 8 * PSTR + 4];
            unsigned q0 = elo[base],     q1 = elo[base + 8 * PSTR];
            unsigned q2 = elo[base + 4], q3 = elo[base + 8 * PSTR + 4];
            mma16(d0, q0, q1, q2, q3, H[kb*2],   H[kb*2+1]);     // Al*Bh
            mma16(d1, q0, q1, q2, q3, H[4+kb*2], H[4+kb*2+1]);
            mma16(d0, a0, a1, a2, a3, L[kb*2],   L[kb*2+1]);     // Ah*Bl
            mma16(d1, a0, a1, a2, a3, L[4+kb*2], L[4+kb*2+1]);
            mma16(d0, a0, a1, a2, a3, H[kb*2],   H[kb*2+1]);     // Ah*Bh
            mma16(d1, a0, a1, a2, a3, H[4+kb*2], H[4+kb*2+1]);
        }
        const int n0a = w * 16;
        if (n0a < 128) {    // warp-uniform: warps 0-7 key channels
            float* kd = sm + SM_K + n0a + 2 * lc;
            *(float2*)(kd + (t0 + lr) * KSTR)         = make_float2(d0[0], d0[1]);
            *(float2*)(kd + (t0 + lr + 8) * KSTR)     = make_float2(d0[2], d0[3]);
            *(float2*)(kd + 8 + (t0 + lr) * KSTR)     = make_float2(d1[0], d1[1]);
            *(float2*)(kd + 8 + (t0 + lr + 8) * KSTR) = make_float2(d1[2], d1[3]);
        } else {            // warps 8,9: value channels
            float* vd = sm + SM_V + (n0a - 128) + 2 * lc;
            *(float2*)(vd + (t0 + lr) * VSTR)         = make_float2(d0[0], d0[1]);
            *(float2*)(vd + (t0 + lr + 8) * VSTR)     = make_float2(d0[2], d0[3]);
            *(float2*)(vd + 8 + (t0 + lr) * VSTR)     = make_float2(d1[0], d1[1]);
            *(float2*)(vd + 8 + (t0 + lr + 8) * VSTR) = make_float2(d1[2], d1[3]);
        }
    }
    __syncthreads();

    // ---- Phase B: 8-lane groups; coalesced hid LDG (1 inst / 4 rows) ----
    {
        const int sub = l >> 3;
        const int lc8 = l & 7;
#pragma unroll 1
        for (int r0 = w * 4; r0 < NITEM; r0 += 40) {
            const int r   = r0 + sub;
            const int tok = r >> 2, g = r & 3;
            const bool valid = (r < NITEM) && (tile_start - HALO + tok >= 0);

            float4 h4 = make_float4(0.f, 0.f, 0.f, 0.f);
            if (valid) h4 = ((const float4*)hbase)[r * 8 + lc8];

            const int c = lc8 * 4;
            ulonglong2 k2 = *(const ulonglong2*)(sm + SM_K + tok * KSTR + g * 32 + c);
            ulonglong2 n2 = *(const ulonglong2*)(sm + SM_NN + g * 32 + c);
            ulonglong2 v2 = *(const ulonglong2*)(sm + SM_V + tok * VSTR + c);
            ull hx = pack2(h4.x, h4.y), hy = pack2(h4.z, h4.w);

            ull skk2 = fma2(k2.y, k2.y, mul2(k2.x, k2.x));
            ull shh2 = fma2(hy, hy, mul2(hx, hx));
            ull skh2 = fma2(mul2(k2.y, hy), n2.y, mul2(mul2(k2.x, hx), n2.x));
            ull svv2 = fma2(v2.y, v2.y, mul2(v2.x, v2.x));

            ull s1 = pack2(lo2(skk2) + hi2(skk2), lo2(shh2) + hi2(shh2));
            ull s2 = pack2(lo2(skh2) + hi2(skh2), lo2(svv2) + hi2(svv2));
#pragma unroll
            for (int off = 1; off < 8; off <<= 1) {
                s1 = add2(s1, __shfl_xor_sync(0xffffffffu, s1, off));
                s2 = add2(s2, __shfl_xor_sync(0xffffffffu, s2, off));
            }
            if (lc8 == 0) {
                float grr = 0.f, gate = 0.f;
                if (valid) {
                    const float skk = lo2(s1), shh = hi2(s1);
                    const float skh = lo2(s2), svv = hi2(s2);
                    const float rs1 = rsqrtf(skk * (1.f/32.f) + EPSF);
                    const float rs2 = rsqrtf(shh * (1.f/32.f) + EPSF);
                    const float dot = skh * rs1 * rs2 * 0.17677669529663687f;
                    const float sq  = fsqrta(fmaxf(fabsf(dot), 1e-6f));
                    const float gs  = (dot > 0.f) ? sq : ((dot < 0.f) ? -sq : 0.f);
                    gate = frcp(1.f + __expf(-gs));
                    grr  = gate * rsqrtf(gate * gate * svv * (1.f/32.f) + EPSF);
                }
                if (r < NITEM) {
                    sm[SM_G + tok * 8 + g * 2 + 0] = grr;
                    sm[SM_G + tok * 8 + g * 2 + 1] = gate;
                }
            }
        }
    }
    __syncthreads();

    // ---- Phase C: conv + SiLU + residual ----
    {
        const int g    = l >> 3;
        const int c0   = (l & 7) * 4;
        const int chb  = g * 32 + c0;
        float4 cw0 = ((const float4*)cvw)[chb + 0];
        float4 cw1 = ((const float4*)cvw)[chb + 1];
        float4 cw2 = ((const float4*)cvw)[chb + 2];
        float4 cw3 = ((const float4*)cvw)[chb + 3];
        ull t9a = pack2(cw0.x, cw1.x), t9b = pack2(cw2.x, cw3.x);
        ull t6a = pack2(cw0.y, cw1.y), t6b = pack2(cw2.y, cw3.y);
        ull t3a = pack2(cw0.z, cw1.z), t3b = pack2(cw2.z, cw3.z);
        ull t0a = pack2(cw0.w, cw1.w), t0b = pack2(cw2.w, cw3.w);
        ull cna = pack2(cnw[chb], cnw[chb+1]), cnb = pack2(cnw[chb+2], cnw[chb+3]);

        for (int mt = w; mt < TILE; mt += 10) {
            const int tok = mt + HALO;
            const float* gp = sm + SM_G;
            const float grr9 = gp[(tok-9)*8 + g*2], grr6 = gp[(tok-6)*8 + g*2];
            const float grr3 = gp[(tok-3)*8 + g*2], grr0 = gp[(tok  )*8 + g*2];
            const float gate = gp[tok*8 + g*2 + 1];
            const ulonglong2 v9 = *(const ulonglong2*)&sm[SM_V + (tok-9)*VSTR + c0];
            const ulonglong2 v6 = *(const ulonglong2*)&sm[SM_V + (tok-6)*VSTR + c0];
            const ulonglong2 v3 = *(const ulonglong2*)&sm[SM_V + (tok-3)*VSTR + c0];
            const ulonglong2 v0 = *(const ulonglong2*)&sm[SM_V + (tok  )*VSTR + c0];
            const ull g92 = pack2(grr9, grr9), g62 = pack2(grr6, grr6);
            const ull g32 = pack2(grr3, grr3), g02 = pack2(grr0, grr0);
            ull ya = mul2(mul2(t9a, v9.x), g92);
            ull yb = mul2(mul2(t9b, v9.y), g92);
            ya = fma2(mul2(t6a, v6.x), g62, ya);
            yb = fma2(mul2(t6b, v6.y), g62, yb);
            ya = fma2(mul2(t3a, v3.x), g32, ya);
            yb = fma2(mul2(t3b, v3.y), g32, yb);
            ya = fma2(mul2(t0a, v0.x), g02, ya);
            yb = fma2(mul2(t0b, v0.y), g02, yb);
            ya = mul2(ya, cna);
            yb = mul2(yb, cnb);
            const float y0 = lo2(ya), y1 = hi2(ya), y2 = lo2(yb), y3 = hi2(yb);
            const float s0 = y0 * frcp(1.f + __expf(-y0));
            const float s1 = y1 * frcp(1.f + __expf(-y1));
            const float s2 = y2 * frcp(1.f + __expf(-y2));
            const float s3 = y3 * frcp(1.f + __expf(-y3));
            float4 o;
            o.x = fmaf(gate, lo2(v0.x), s0);
            o.y = fmaf(gate, hi2(v0.x), s1);
            o.z = fmaf(gate, lo2(v0.y), s2);
            o.w = fmaf(gate, hi2(v0.y), s3);
            ((float4*)out)[(((base_tok + mt) * 4 + g) * 32 + c0) >> 2] = o;
        }
    }
}

extern "C" void kernel_launch(void* const* d_in, const int* in_sizes, int n_in,
                              void* d_out, int out_size)
{
    const float* emb = (const float*)d_in[0];
    const float* hid = (const float*)d_in[1];
    const float* Wv  = (const float*)d_in[2];
    const float* bv  = (const float*)d_in[3];
    const float* Wk  = (const float*)d_in[4];
    const float* bk  = (const float*)d_in[5];
    const float* n1w = (const float*)d_in[6];
    const float* n2w = (const float*)d_in[7];
    const float* cnw = (const float*)d_in[8];
    const float* cvw = (const float*)d_in[9];
    float* out = (float*)d_out;

    const int T = 8192;
    const int B = in_sizes[0] / (T * 32);
    const size_t smem = SM_FLOATS * sizeof(float);   // 69440 B

    cudaFuncSetAttribute(engram_kernel,
                         cudaFuncAttributeMaxDynamicSharedMemorySize, (int)smem);

    dim3 grid(T / TILE, B);
    engram_kernel<<<grid, 320, smem>>>(emb, hid, Wv, bv, Wk, bk,
                                       n1w, n2w, cnw, cvw, out, T);
}

// round 13
// speedup vs baseline: 1.1413x; 1.0373x over previous
#include <cuda_runtime.h>

#define EPSF 1.1920929e-07f
typedef unsigned long long ull;

constexpr int TILE  = 64;
constexpr int HALO  = 10;
constexpr int NROWS = 80;          // token rows (5 x m16 tiles)
constexpr int NGATE = 74;          // TILE + HALO
constexpr int NITEM = NGATE * 4;   // 296 (tok,g) items
constexpr int KSTR  = 132;
constexpr int VSTR  = 36;

// shared layout (32-bit word offsets)
constexpr int SM_EHI = 0;                      // [10][32][4] frag-ordered (m,kb)
constexpr int SM_ELO = SM_EHI + 1280;          // [10][32][4]
constexpr int SM_K   = SM_ELO + 1280;          // [80][132] f32 keys
constexpr int SM_V   = SM_K + NROWS * KSTR;    // [80][36] f32 values
constexpr int SM_G   = SM_V + NROWS * VSTR;    // [74][4][2] (grr, gate)
constexpr int SM_NN  = SM_G + NGATE * 8;       // [128] n1*n2
constexpr int SM_FLOATS = SM_NN + 128;         // 16720 words = 66880 B

__device__ __forceinline__ ull fma2(ull a, ull b, ull c) {
    ull d; asm("fma.rn.f32x2 %0, %1, %2, %3;" : "=l"(d) : "l"(a), "l"(b), "l"(c)); return d;
}
__device__ __forceinline__ ull mul2(ull a, ull b) {
    ull d; asm("mul.rn.f32x2 %0, %1, %2;" : "=l"(d) : "l"(a), "l"(b)); return d;
}
__device__ __forceinline__ ull add2(ull a, ull b) {
    ull d; asm("add.rn.f32x2 %0, %1, %2;" : "=l"(d) : "l"(a), "l"(b)); return d;
}
__device__ __forceinline__ ull pack2(float x, float y) {
    ull r; asm("mov.b64 %0, {%1, %2};" : "=l"(r) : "f"(x), "f"(y)); return r;
}
__device__ __forceinline__ float lo2(ull a) { float2 f = *(float2*)&a; return f.x; }
__device__ __forceinline__ float hi2(ull a) { float2 f = *(float2*)&a; return f.y; }
__device__ __forceinline__ float fsqrta(float x) {
    float r; asm("sqrt.approx.f32 %0, %1;" : "=f"(r) : "f"(x)); return r;
}
__device__ __forceinline__ float tanha(float x) {
    float r; asm("tanh.approx.f32 %0, %1;" : "=f"(r) : "f"(x)); return r;
}

__device__ __forceinline__ void split_bf16x2(float x0, float x1,
                                             unsigned& uh, unsigned& ul) {
    unsigned h;
    asm("cvt.rn.bf16x2.f32 %0, %1, %2;" : "=r"(h) : "f"(x1), "f"(x0));
    float h0 = __uint_as_float(h << 16);
    float h1 = __uint_as_float(h & 0xffff0000u);
    float l0 = x0 - h0, l1 = x1 - h1;
    asm("cvt.rn.bf16x2.f32 %0, %1, %2;" : "=r"(ul) : "f"(l1), "f"(l0));
    uh = h;
}

__device__ __forceinline__ void mma16(float* d, unsigned a0, unsigned a1,
                                      unsigned a2, unsigned a3,
                                      unsigned b0, unsigned b1) {
    asm volatile("mma.sync.aligned.m16n8k16.row.col.f32.bf16.bf16.f32 "
                 "{%0,%1,%2,%3}, {%4,%5,%6,%7}, {%8,%9}, {%0,%1,%2,%3};"
                 : "+f"(d[0]), "+f"(d[1]), "+f"(d[2]), "+f"(d[3])
                 : "r"(a0), "r"(a1), "r"(a2), "r"(a3), "r"(b0), "r"(b1));
}

__global__ void __launch_bounds__(320, 3)
engram_kernel(const float* __restrict__ emb, const float* __restrict__ hid,
              const float* __restrict__ Wv,  const float* __restrict__ bv,
              const float* __restrict__ Wk,  const float* __restrict__ bk,
              const float* __restrict__ n1w, const float* __restrict__ n2w,
              const float* __restrict__ cnw, const float* __restrict__ cvw,
              float* __restrict__ out, int T)
{
    extern __shared__ float sm[];
    unsigned* ehi = (unsigned*)(sm + SM_EHI);
    unsigned* elo = (unsigned*)(sm + SM_ELO);

    const int tid        = threadIdx.x;
    const int b          = blockIdx.y;
    const int tile_start = blockIdx.x * TILE;
    const long base_tok  = (long)b * T + tile_start;
    const float* hbase   = hid + (base_tok - HALO) * 128;

    const int w  = tid >> 5, l = tid & 31;
    const int lr = l >> 2, lc = l & 3;

    // ---- per-thread B fragments + bias, computed straight from weights ----
    unsigned H[8], L[8];
#pragma unroll
    for (int i = 0; i < 8; i++) {
        const int j = i >> 2, kb = (i >> 1) & 1, idx = i & 1;
        const int row = w * 16 + j * 8 + lr;
        const int t   = kb * 8 + lc + idx * 4;      // channel pair (2t, 2t+1)
        const float* src = (row < 128) ? (Wk + row * 32) : (Wv + (row - 128) * 32);
        float2 p = *(const float2*)(src + 2 * t);
        split_bf16x2(p.x, p.y, H[i], L[i]);
    }
    float4 bf;
    {
        const int n0 = w * 16, n1 = w * 16 + 8;
        const float* b0 = (n0 < 128) ? (bk + n0) : (bv + n0 - 128);
        const float* b1 = (n1 < 128) ? (bk + n1) : (bv + n1 - 128);
        bf = make_float4(b0[2 * lc], b0[2 * lc + 1], b1[2 * lc], b1[2 * lc + 1]);
    }

    // ---- stage emb (hi/lo bf16x2) in MMA-fragment order + nn ----
    for (int i4 = tid; i4 < NROWS * 8; i4 += 320) {
        int tok = i4 >> 3, q = i4 & 7;
        int gt  = tile_start - HALO + tok;
        float4 val = make_float4(0.f, 0.f, 0.f, 0.f);
        if (tok < NGATE && gt >= 0)
            val = ((const float4*)emb)[(base_tok - HALO + tok) * 8 + q];
        unsigned h0, l0, h1, l1;
        split_bf16x2(val.x, val.y, h0, l0);      // pair p = 2q
        split_bf16x2(val.z, val.w, h1, l1);      // pair p+1
        const int m = tok >> 4, r = tok & 15;
        const int half = r >> 3, plr = r & 7;
        const int p = 2 * q;
        const int kb = p >> 3, idx = (p >> 2) & 1, plc = p & 3;
        const int addr = (m * 2 + kb) * 128 + (plr * 4 + plc) * 4 + half + 2 * idx;
        ehi[addr] = h0; elo[addr] = l0;
        ehi[addr + 4] = h1; elo[addr + 4] = l1;  // pair p+1 -> plc+1
    }
    if (tid < 128) sm[SM_NN + tid] = n1w[tid] * n2w[tid];
    __syncthreads();

    // ---- Phase A: 3-term bf16 mma; A-frags via single LDS.128 ----
#pragma unroll 1
    for (int m = 0; m < 5; m++) {
        const int t0 = m * 16;
        float d0[4], d1[4];
        d0[0] = bf.x; d0[1] = bf.y; d0[2] = bf.x; d0[3] = bf.y;
        d1[0] = bf.z; d1[1] = bf.w; d1[2] = bf.z; d1[3] = bf.w;
#pragma unroll
        for (int kb = 0; kb < 2; kb++) {
            const int fb = (m * 2 + kb) * 128 + l * 4;
            uint4 A = *(const uint4*)(ehi + fb);
            uint4 Q = *(const uint4*)(elo + fb);
            mma16(d0, Q.x, Q.y, Q.z, Q.w, H[kb*2],   H[kb*2+1]);   // Al*Bh
            mma16(d1, Q.x, Q.y, Q.z, Q.w, H[4+kb*2], H[4+kb*2+1]);
            mma16(d0, A.x, A.y, A.z, A.w, L[kb*2],   L[kb*2+1]);   // Ah*Bl
            mma16(d1, A.x, A.y, A.z, A.w, L[4+kb*2], L[4+kb*2+1]);
            mma16(d0, A.x, A.y, A.z, A.w, H[kb*2],   H[kb*2+1]);   // Ah*Bh
            mma16(d1, A.x, A.y, A.z, A.w, H[4+kb*2], H[4+kb*2+1]);
        }
        const int n0a = w * 16;
        if (n0a < 128) {    // warp-uniform: warps 0-7 key channels
            float* kd = sm + SM_K + n0a + 2 * lc;
            *(float2*)(kd + (t0 + lr) * KSTR)         = make_float2(d0[0], d0[1]);
            *(float2*)(kd + (t0 + lr + 8) * KSTR)     = make_float2(d0[2], d0[3]);
            *(float2*)(kd + 8 + (t0 + lr) * KSTR)     = make_float2(d1[0], d1[1]);
            *(float2*)(kd + 8 + (t0 + lr + 8) * KSTR) = make_float2(d1[2], d1[3]);
        } else {            // warps 8,9: value channels
            float* vd = sm + SM_V + (n0a - 128) + 2 * lc;
            *(float2*)(vd + (t0 + lr) * VSTR)         = make_float2(d0[0], d0[1]);
            *(float2*)(vd + (t0 + lr + 8) * VSTR)     = make_float2(d0[2], d0[3]);
            *(float2*)(vd + 8 + (t0 + lr) * VSTR)     = make_float2(d1[0], d1[1]);
            *(float2*)(vd + 8 + (t0 + lr + 8) * VSTR) = make_float2(d1[2], d1[3]);
        }
    }
    __syncthreads();

    // ---- Phase B: 8-lane groups; coalesced hid LDG (1 inst / 4 rows) ----
    {
        const int sub = l >> 3;
        const int lc8 = l & 7;
#pragma unroll 1
        for (int r0 = w * 4; r0 < NITEM; r0 += 40) {
            const int r   = r0 + sub;
            const int tok = r >> 2, g = r & 3;
            const bool valid = (r < NITEM) && (tile_start - HALO + tok >= 0);

            float4 h4 = make_float4(0.f, 0.f, 0.f, 0.f);
            if (valid) h4 = ((const float4*)hbase)[r * 8 + lc8];

            const int c = lc8 * 4;
            ulonglong2 k2 = *(const ulonglong2*)(sm + SM_K + tok * KSTR + g * 32 + c);
            ulonglong2 n2 = *(const ulonglong2*)(sm + SM_NN + g * 32 + c);
            ulonglong2 v2 = *(const ulonglong2*)(sm + SM_V + tok * VSTR + c);
            ull hx = pack2(h4.x, h4.y), hy = pack2(h4.z, h4.w);

            ull skk2 = fma2(k2.y, k2.y, mul2(k2.x, k2.x));
            ull shh2 = fma2(hy, hy, mul2(hx, hx));
            ull skh2 = fma2(mul2(k2.y, hy), n2.y, mul2(mul2(k2.x, hx), n2.x));
            ull svv2 = fma2(v2.y, v2.y, mul2(v2.x, v2.x));

            ull s1 = pack2(lo2(skk2) + hi2(skk2), lo2(shh2) + hi2(shh2));
            ull s2 = pack2(lo2(skh2) + hi2(skh2), lo2(svv2) + hi2(svv2));
#pragma unroll
            for (int off = 1; off < 8; off <<= 1) {
                s1 = add2(s1, __shfl_xor_sync(0xffffffffu, s1, off));
                s2 = add2(s2, __shfl_xor_sync(0xffffffffu, s2, off));
            }
            if (lc8 == 0) {
                float grr = 0.f, gate = 0.f;
                if (valid) {
                    const float skk = lo2(s1), shh = hi2(s1);
                    const float skh = lo2(s2), svv = hi2(s2);
                    const float rs1 = rsqrtf(skk * (1.f/32.f) + EPSF);
                    const float rs2 = rsqrtf(shh * (1.f/32.f) + EPSF);
                    const float dot = skh * rs1 * rs2 * 0.17677669529663687f;
                    const float sq  = fsqrta(fmaxf(fabsf(dot), 1e-6f));
                    const float gs  = (dot > 0.f) ? sq : ((dot < 0.f) ? -sq : 0.f);
                    gate = fmaf(0.5f, tanha(0.5f * gs), 0.5f);   // sigmoid(gs)
                    grr  = gate * rsqrtf(gate * gate * svv * (1.f/32.f) + EPSF);
                }
                if (r < NITEM) {
                    sm[SM_G + tok * 8 + g * 2 + 0] = grr;
                    sm[SM_G + tok * 8 + g * 2 + 1] = gate;
                }
            }
        }
    }
    __syncthreads();

    // ---- Phase C: conv + tanh-SiLU + residual ----
    {
        const int g    = l >> 3;
        const int c0   = (l & 7) * 4;
        const int chb  = g * 32 + c0;
        float4 cw0 = ((const float4*)cvw)[chb + 0];
        float4 cw1 = ((const float4*)cvw)[chb + 1];
        float4 cw2 = ((const float4*)cvw)[chb + 2];
        float4 cw3 = ((const float4*)cvw)[chb + 3];
        ull t9a = pack2(cw0.x, cw1.x), t9b = pack2(cw2.x, cw3.x);
        ull t6a = pack2(cw0.y, cw1.y), t6b = pack2(cw2.y, cw3.y);
        ull t3a = pack2(cw0.z, cw1.z), t3b = pack2(cw2.z, cw3.z);
        ull t0a = pack2(cw0.w, cw1.w), t0b = pack2(cw2.w, cw3.w);
        ull cna = pack2(cnw[chb], cnw[chb+1]), cnb = pack2(cnw[chb+2], cnw[chb+3]);
        const ull HALF2 = pack2(0.5f, 0.5f);

        for (int mt = w; mt < TILE; mt += 10) {
            const int tok = mt + HALO;
            const float* gp = sm + SM_G;
            const float grr9 = gp[(tok-9)*8 + g*2], grr6 = gp[(tok-6)*8 + g*2];
            const float grr3 = gp[(tok-3)*8 + g*2], grr0 = gp[(tok  )*8 + g*2];
            const float gate = gp[tok*8 + g*2 + 1];
            const ulonglong2 v9 = *(const ulonglong2*)&sm[SM_V + (tok-9)*VSTR + c0];
            const ulonglong2 v6 = *(const ulonglong2*)&sm[SM_V + (tok-6)*VSTR + c0];
            const ulonglong2 v3 = *(const ulonglong2*)&sm[SM_V + (tok-3)*VSTR + c0];
            const ulonglong2 v0 = *(const ulonglong2*)&sm[SM_V + (tok  )*VSTR + c0];
            const ull g92 = pack2(grr9, grr9), g62 = pack2(grr6, grr6);
            const ull g32 = pack2(grr3, grr3), g02 = pack2(grr0, grr0);
            ull ya = mul2(mul2(t9a, v9.x), g92);
            ull yb = mul2(mul2(t9b, v9.y), g92);
            ya = fma2(mul2(t6a, v6.x), g62, ya);
            yb = fma2(mul2(t6b, v6.y), g62, yb);
            ya = fma2(mul2(t3a, v3.x), g32, ya);
            yb = fma2(mul2(t3b, v3.y), g32, yb);
            ya = fma2(mul2(t0a, v0.x), g02, ya);
            yb = fma2(mul2(t0b, v0.y), g02, yb);
            ya = mul2(ya, cna);
            yb = mul2(yb, cnb);
            // silu(y) = hy + hy*tanh(hy), hy = y/2
            ull hya = mul2(ya, HALF2);
            ull hyb = mul2(yb, HALF2);
            ull ta = pack2(tanha(lo2(hya)), tanha(hi2(hya)));
            ull tb = pack2(tanha(lo2(hyb)), tanha(hi2(hyb)));
            ull sa = fma2(hya, ta, hya);
            ull sb = fma2(hyb, tb, hyb);
            float4 o;
            o.x = fmaf(gate, lo2(v0.x), lo2(sa));
            o.y = fmaf(gate, hi2(v0.x), hi2(sa));
            o.z = fmaf(gate, lo2(v0.y), lo2(sb));
            o.w = fmaf(gate, hi2(v0.y), hi2(sb));
            ((float4*)out)[(((base_tok + mt) * 4 + g) * 32 + c0) >> 2] = o;
        }
    }
}

extern "C" void kernel_launch(void* const* d_in, const int* in_sizes, int n_in,
                              void* d_out, int out_size)
{
    const float* emb = (const float*)d_in[0];
    const float* hid = (const float*)d_in[1];
    const float* Wv  = (const float*)d_in[2];
    const float* bv  = (const float*)d_in[3];
    const float* Wk  = (const float*)d_in[4];
    const float* bk  = (const float*)d_in[5];
    const float* n1w = (const float*)d_in[6];
    const float* n2w = (const float*)d_in[7];
    const float* cnw = (const float*)d_in[8];
    const float* cvw = (const float*)d_in[9];
    float* out = (float*)d_out;

    const int T = 8192;
    const int B = in_sizes[0] / (T * 32);
    const size_t smem = SM_FLOATS * sizeof(float);   // 66880 B

    cudaFuncSetAttribute(engram_kernel,
                         cudaFuncAttributeMaxDynamicSharedMemorySize, (int)smem);

    dim3 grid(T / TILE, B);
    engram_kernel<<<grid, 320, smem>>>(emb, hid, Wv, bv, Wk, bk,
                                       n1w, n2w, cnw, cvw, out, T);
}

// round 15
// speedup vs baseline: 1.2983x; 1.1375x over previous
#include <cuda_runtime.h>

#define EPSF 1.1920929e-07f
typedef unsigned long long ull;

constexpr int TILE  = 64;
constexpr int HALO  = 10;
constexpr int NROWS = 80;          // token rows (5 x m16 tiles)
constexpr int NGATE = 74;          // TILE + HALO
constexpr int NITEM = NGATE * 4;   // 296 (tok,g) items
constexpr int VSTR  = 36;
constexpr int PSTRW = 68;          // SM_P per-token stride (bank spread)
constexpr int HSTRW = 36;          // SM_HH per-token stride

// shared layout (32-bit word offsets)
constexpr int SM_EHI = 0;                      // [10][32][4] frag-ordered emb hi
constexpr int SM_ELO = SM_EHI + 1280;          // [10][32][4] emb lo
constexpr int SM_V   = SM_ELO + 1280;          // [80][36] f32 values
constexpr int SM_G   = SM_V + NROWS * VSTR;    // [74][4][2] (grr, gate)
constexpr int SM_P   = SM_G + NGATE * 8;       // [80][68] (skk,skh) float2 x8x4
constexpr int SM_HH  = SM_P + NROWS * PSTRW;   // [80][36] shh partials
constexpr int SM_VV  = SM_HH + NROWS * HSTRW;  // [80][8]  svv partials
constexpr int SM_FLOATS = SM_VV + NROWS * 8;   // 14992 words = 59968 B

__device__ __forceinline__ ull fma2(ull a, ull b, ull c) {
    ull d; asm("fma.rn.f32x2 %0, %1, %2, %3;" : "=l"(d) : "l"(a), "l"(b), "l"(c)); return d;
}
__device__ __forceinline__ ull mul2(ull a, ull b) {
    ull d; asm("mul.rn.f32x2 %0, %1, %2;" : "=l"(d) : "l"(a), "l"(b)); return d;
}
__device__ __forceinline__ ull add2(ull a, ull b) {
    ull d; asm("add.rn.f32x2 %0, %1, %2;" : "=l"(d) : "l"(a), "l"(b)); return d;
}
__device__ __forceinline__ ull pack2(float x, float y) {
    ull r; asm("mov.b64 %0, {%1, %2};" : "=l"(r) : "f"(x), "f"(y)); return r;
}
__device__ __forceinline__ float lo2(ull a) { float2 f = *(float2*)&a; return f.x; }
__device__ __forceinline__ float hi2(ull a) { float2 f = *(float2*)&a; return f.y; }
__device__ __forceinline__ float fsqrta(float x) {
    float r; asm("sqrt.approx.f32 %0, %1;" : "=f"(r) : "f"(x)); return r;
}
__device__ __forceinline__ float tanha(float x) {
    float r; asm("tanh.approx.f32 %0, %1;" : "=f"(r) : "f"(x)); return r;
}

__device__ __forceinline__ void split_bf16x2(float x0, float x1,
                                             unsigned& uh, unsigned& ul) {
    unsigned h;
    asm("cvt.rn.bf16x2.f32 %0, %1, %2;" : "=r"(h) : "f"(x1), "f"(x0));
    float h0 = __uint_as_float(h << 16);
    float h1 = __uint_as_float(h & 0xffff0000u);
    float l0 = x0 - h0, l1 = x1 - h1;
    asm("cvt.rn.bf16x2.f32 %0, %1, %2;" : "=r"(ul) : "f"(l1), "f"(l0));
    uh = h;
}

__device__ __forceinline__ void mma16(float* d, unsigned a0, unsigned a1,
                                      unsigned a2, unsigned a3,
                                      unsigned b0, unsigned b1) {
    asm volatile("mma.sync.aligned.m16n8k16.row.col.f32.bf16.bf16.f32 "
                 "{%0,%1,%2,%3}, {%4,%5,%6,%7}, {%8,%9}, {%0,%1,%2,%3};"
                 : "+f"(d[0]), "+f"(d[1]), "+f"(d[2]), "+f"(d[3])
                 : "r"(a0), "r"(a1), "r"(a2), "r"(a3), "r"(b0), "r"(b1));
}

__global__ void __launch_bounds__(320, 3)
engram_kernel(const float* __restrict__ emb, const float* __restrict__ hid,
              const float* __restrict__ Wv,  const float* __restrict__ bv,
              const float* __restrict__ Wk,  const float* __restrict__ bk,
              const float* __restrict__ n1w, const float* __restrict__ n2w,
              const float* __restrict__ cnw, const float* __restrict__ cvw,
              float* __restrict__ out, int T)
{
    extern __shared__ float sm[];
    unsigned* ehi = (unsigned*)(sm + SM_EHI);
    unsigned* elo = (unsigned*)(sm + SM_ELO);

    const int tid        = threadIdx.x;
    const int b          = blockIdx.y;
    const int tile_start = blockIdx.x * TILE;
    const long base_tok  = (long)b * T + tile_start;
    const float* hbase   = hid + (base_tok - HALO) * 128;

    const int w  = tid >> 5, l = tid & 31;
    const int lr = l >> 2, lc = l & 3;

    // ---- per-thread B fragments + bias from weights ----
    unsigned H[8], L[8];
#pragma unroll
    for (int i = 0; i < 8; i++) {
        const int j = i >> 2, kb = (i >> 1) & 1, idx = i & 1;
        const int row = w * 16 + j * 8 + lr;
        const int t   = kb * 8 + lc + idx * 4;
        const float* src = (row < 128) ? (Wk + row * 32) : (Wv + (row - 128) * 32);
        float2 p = *(const float2*)(src + 2 * t);
        split_bf16x2(p.x, p.y, H[i], L[i]);
    }
    float4 bf;
    {
        const int n0 = w * 16, n1 = w * 16 + 8;
        const float* b0 = (n0 < 128) ? (bk + n0) : (bv + n0 - 128);
        const float* b1 = (n1 < 128) ? (bk + n1) : (bv + n1 - 128);
        bf = make_float4(b0[2 * lc], b0[2 * lc + 1], b1[2 * lc], b1[2 * lc + 1]);
    }
    // nn pairs for this thread's key columns (warps 0-7 only use these)
    ull NN0 = 0, NN8 = 0;
    if (w < 8) {
        const int chb2 = w * 16 + 2 * lc;
        float2 a1 = *(const float2*)(n1w + chb2);
        float2 a2 = *(const float2*)(n2w + chb2);
        float2 b1 = *(const float2*)(n1w + chb2 + 8);
        float2 b2 = *(const float2*)(n2w + chb2 + 8);
        NN0 = pack2(a1.x * a2.x, a1.y * a2.y);
        NN8 = pack2(b1.x * b2.x, b1.y * b2.y);
    }

    // ---- stage emb (hi/lo bf16x2) in MMA-fragment order ----
    for (int i4 = tid; i4 < NROWS * 8; i4 += 320) {
        int tok = i4 >> 3, q = i4 & 7;
        int gt  = tile_start - HALO + tok;
        float4 val = make_float4(0.f, 0.f, 0.f, 0.f);
        if (tok < NGATE && gt >= 0)
            val = ((const float4*)emb)[(base_tok - HALO + tok) * 8 + q];
        unsigned h0, l0, h1, l1;
        split_bf16x2(val.x, val.y, h0, l0);
        split_bf16x2(val.z, val.w, h1, l1);
        const int m = tok >> 4, r = tok & 15;
        const int half = r >> 3, plr = r & 7;
        const int p = 2 * q;
        const int kb = p >> 3, idx = (p >> 2) & 1, plc = p & 3;
        const int addr = (m * 2 + kb) * 128 + (plr * 4 + plc) * 4 + half + 2 * idx;
        ehi[addr] = h0; elo[addr] = l0;
        ehi[addr + 4] = h1; elo[addr + 4] = l1;
    }
    __syncthreads();

    // ---- Phase A: MMA + in-register norm partials ----
#pragma unroll 1
    for (int m = 0; m < 5; m++) {
        const int t0 = m * 16;
        const int tk1 = t0 + lr, tk2 = tk1 + 8;

        // h loads for this thread's (row, col) fragment positions (warps 0-7)
        float2 h1a = make_float2(0.f, 0.f), h1b = h1a, h2a = h1a, h2b = h1a;
        if (w < 8) {
            const int coff = w * 16 + 2 * lc;
            const float* hp1 = hbase + tk1 * 128 + coff;
            const float* hp2 = hbase + tk2 * 128 + coff;
            if (tk1 < NGATE && tile_start - HALO + tk1 >= 0) {
                h1a = *(const float2*)hp1;
                h1b = *(const float2*)(hp1 + 8);
            }
            if (tk2 < NGATE && tile_start - HALO + tk2 >= 0) {
                h2a = *(const float2*)hp2;
                h2b = *(const float2*)(hp2 + 8);
            }
        }

        float d0[4], d1[4];
        d0[0] = bf.x; d0[1] = bf.y; d0[2] = bf.x; d0[3] = bf.y;
        d1[0] = bf.z; d1[1] = bf.w; d1[2] = bf.z; d1[3] = bf.w;
#pragma unroll
        for (int kb = 0; kb < 2; kb++) {
            const int fb = (m * 2 + kb) * 128 + l * 4;
            uint4 A = *(const uint4*)(ehi + fb);
            uint4 Q = *(const uint4*)(elo + fb);
            mma16(d0, Q.x, Q.y, Q.z, Q.w, H[kb*2],   H[kb*2+1]);   // Al*Bh
            mma16(d1, Q.x, Q.y, Q.z, Q.w, H[4+kb*2], H[4+kb*2+1]);
            mma16(d0, A.x, A.y, A.z, A.w, L[kb*2],   L[kb*2+1]);   // Ah*Bl
            mma16(d1, A.x, A.y, A.z, A.w, L[4+kb*2], L[4+kb*2+1]);
            mma16(d0, A.x, A.y, A.z, A.w, H[kb*2],   H[kb*2+1]);   // Ah*Bh
            mma16(d1, A.x, A.y, A.z, A.w, H[4+kb*2], H[4+kb*2+1]);
        }

        ull D1a = pack2(d0[0], d0[1]), D1b = pack2(d1[0], d1[1]);
        ull D2a = pack2(d0[2], d0[3]), D2b = pack2(d1[2], d1[3]);

        if (w < 8) {   // key channels: skk/skh/shh partials
            ull H1a = pack2(h1a.x, h1a.y), H1b = pack2(h1b.x, h1b.y);
            ull H2a = pack2(h2a.x, h2a.y), H2b = pack2(h2b.x, h2b.y);
            ull HN1a = mul2(H1a, NN0), HN1b = mul2(H1b, NN8);
            ull HN2a = mul2(H2a, NN0), HN2b = mul2(H2b, NN8);

            ull skk1 = fma2(D1b, D1b, mul2(D1a, D1a));
            ull skh1 = fma2(D1b, HN1b, mul2(D1a, HN1a));
            ull shh1 = fma2(H1b, H1b, mul2(H1a, H1a));
            ull skk2 = fma2(D2b, D2b, mul2(D2a, D2a));
            ull skh2 = fma2(D2b, HN2b, mul2(D2a, HN2a));
            ull shh2 = fma2(H2b, H2b, mul2(H2a, H2a));

            *(float2*)(sm + SM_P + tk1 * PSTRW + w * 8 + lc * 2) =
                make_float2(lo2(skk1) + hi2(skk1), lo2(skh1) + hi2(skh1));
            *(float2*)(sm + SM_P + tk2 * PSTRW + w * 8 + lc * 2) =
                make_float2(lo2(skk2) + hi2(skk2), lo2(skh2) + hi2(skh2));
            sm[SM_HH + tk1 * HSTRW + w * 4 + lc] = lo2(shh1) + hi2(shh1);
            sm[SM_HH + tk2 * HSTRW + w * 4 + lc] = lo2(shh2) + hi2(shh2);
        } else {       // value channels: V stores + svv partials
            float* vd = sm + SM_V + (w - 8) * 16 + 2 * lc;
            *(float2*)(vd + tk1 * VSTR)     = *(float2*)&D1a;
            *(float2*)(vd + tk2 * VSTR)     = *(float2*)&D2a;
            *(float2*)(vd + 8 + tk1 * VSTR) = *(float2*)&D1b;
            *(float2*)(vd + 8 + tk2 * VSTR) = *(float2*)&D2b;
            ull svv1 = fma2(D1b, D1b, mul2(D1a, D1a));
            ull svv2 = fma2(D2b, D2b, mul2(D2a, D2a));
            sm[SM_VV + tk1 * 8 + (w - 8) * 4 + lc] = lo2(svv1) + hi2(svv1);
            sm[SM_VV + tk2 * 8 + (w - 8) * 4 + lc] = lo2(svv2) + hi2(svv2);
        }
    }
    __syncthreads();

    // ---- Phase B: tiny — combine partials, compute gate/grr ----
    if (tid < NITEM) {
        const int tok = tid >> 2, g = tid & 3;
        float grr = 0.f, gate = 0.f;
        if (tile_start - HALO + tok >= 0) {
            // skk/skh: 16 floats (8 float2) from warps 2g, 2g+1
            const ulonglong2* pk = (const ulonglong2*)(sm + SM_P + tok * PSTRW + g * 16);
            ulonglong2 a = pk[0], b2 = pk[1], c2 = pk[2], d2 = pk[3];
            ull s = add2(add2(add2(a.x, a.y), add2(b2.x, b2.y)),
                         add2(add2(c2.x, c2.y), add2(d2.x, d2.y)));
            // shh: 8 floats
            const ulonglong2* ph = (const ulonglong2*)(sm + SM_HH + tok * HSTRW + g * 8);
            ulonglong2 hh0 = ph[0], hh1 = ph[1];
            ull sh2 = add2(add2(hh0.x, hh0.y), add2(hh1.x, hh1.y));
            // svv: 8 floats
            const ulonglong2* pv = (const ulonglong2*)(sm + SM_VV + tok * 8);
            ulonglong2 vv0 = pv[0], vv1 = pv[1];
            ull sv2 = add2(add2(vv0.x, vv0.y), add2(vv1.x, vv1.y));

            const float skk = lo2(s), skh = hi2(s);
            const float shh = lo2(sh2) + hi2(sh2);
            const float svv = lo2(sv2) + hi2(sv2);
            const float rs1 = rsqrtf(skk * (1.f/32.f) + EPSF);
            const float rs2 = rsqrtf(shh * (1.f/32.f) + EPSF);
            const float dot = skh * rs1 * rs2 * 0.17677669529663687f;
            const float sq  = fsqrta(fmaxf(fabsf(dot), 1e-6f));
            const float gs  = (dot > 0.f) ? sq : ((dot < 0.f) ? -sq : 0.f);
            gate = fmaf(0.5f, tanha(0.5f * gs), 0.5f);   // sigmoid(gs)
            grr  = gate * rsqrtf(gate * gate * svv * (1.f/32.f) + EPSF);
        }
        sm[SM_G + tok * 8 + g * 2 + 0] = grr;
        sm[SM_G + tok * 8 + g * 2 + 1] = gate;
    }
    __syncthreads();

    // ---- Phase C: conv + tanh-SiLU + residual ----
    {
        const int g    = l >> 3;
        const int c0   = (l & 7) * 4;
        const int chb  = g * 32 + c0;
        float4 cw0 = ((const float4*)cvw)[chb + 0];
        float4 cw1 = ((const float4*)cvw)[chb + 1];
        float4 cw2 = ((const float4*)cvw)[chb + 2];
        float4 cw3 = ((const float4*)cvw)[chb + 3];
        ull t9a = pack2(cw0.x, cw1.x), t9b = pack2(cw2.x, cw3.x);
        ull t6a = pack2(cw0.y, cw1.y), t6b = pack2(cw2.y, cw3.y);
        ull t3a = pack2(cw0.z, cw1.z), t3b = pack2(cw2.z, cw3.z);
        ull t0a = pack2(cw0.w, cw1.w), t0b = pack2(cw2.w, cw3.w);
        ull cna = pack2(cnw[chb], cnw[chb+1]), cnb = pack2(cnw[chb+2], cnw[chb+3]);
        const ull HALF2 = pack2(0.5f, 0.5f);

        for (int mt = w; mt < TILE; mt += 10) {
            const int tok = mt + HALO;
            const float* gp = sm + SM_G;
            const float grr9 = gp[(tok-9)*8 + g*2], grr6 = gp[(tok-6)*8 + g*2];
            const float grr3 = gp[(tok-3)*8 + g*2], grr0 = gp[(tok  )*8 + g*2];
            const float gate = gp[tok*8 + g*2 + 1];
            const ulonglong2 v9 = *(const ulonglong2*)&sm[SM_V + (tok-9)*VSTR + c0];
            const ulonglong2 v6 = *(const ulonglong2*)&sm[SM_V + (tok-6)*VSTR + c0];
            const ulonglong2 v3 = *(const ulonglong2*)&sm[SM_V + (tok-3)*VSTR + c0];
            const ulonglong2 v0 = *(const ulonglong2*)&sm[SM_V + (tok  )*VSTR + c0];
            const ull g92 = pack2(grr9, grr9), g62 = pack2(grr6, grr6);
            const ull g32 = pack2(grr3, grr3), g02 = pack2(grr0, grr0);
            ull ya = mul2(mul2(t9a, v9.x), g92);
            ull yb = mul2(mul2(t9b, v9.y), g92);
            ya = fma2(mul2(t6a, v6.x), g62, ya);
            yb = fma2(mul2(t6b, v6.y), g62, yb);
            ya = fma2(mul2(t3a, v3.x), g32, ya);
            yb = fma2(mul2(t3b, v3.y), g32, yb);
            ya = fma2(mul2(t0a, v0.x), g02, ya);
            yb = fma2(mul2(t0b, v0.y), g02, yb);
            ya = mul2(ya, cna);
            yb = mul2(yb, cnb);
            ull hya = mul2(ya, HALF2);
            ull hyb = mul2(yb, HALF2);
            ull ta = pack2(tanha(lo2(hya)), tanha(hi2(hya)));
            ull tb = pack2(tanha(lo2(hyb)), tanha(hi2(hyb)));
            ull sa = fma2(hya, ta, hya);
            ull sb = fma2(hyb, tb, hyb);
            float4 o;
            o.x = fmaf(gate, lo2(v0.x), lo2(sa));
            o.y = fmaf(gate, hi2(v0.x), hi2(sa));
            o.z = fmaf(gate, lo2(v0.y), lo2(sb));
            o.w = fmaf(gate, hi2(v0.y), hi2(sb));
            ((float4*)out)[(((base_tok + mt) * 4 + g) * 32 + c0) >> 2] = o;
        }
    }
}

extern "C" void kernel_launch(void* const* d_in, const int* in_sizes, int n_in,
                              void* d_out, int out_size)
{
    const float* emb = (const float*)d_in[0];
    const float* hid = (const float*)d_in[1];
    const float* Wv  = (const float*)d_in[2];
    const float* bv  = (const float*)d_in[3];
    const float* Wk  = (const float*)d_in[4];
    const float* bk  = (const float*)d_in[5];
    const float* n1w = (const float*)d_in[6];
    const float* n2w = (const float*)d_in[7];
    const float* cnw = (const float*)d_in[8];
    const float* cvw = (const float*)d_in[9];
    float* out = (float*)d_out;

    const int T = 8192;
    const int B = in_sizes[0] / (T * 32);
    const size_t smem = SM_FLOATS * sizeof(float);   // 59968 B

    cudaFuncSetAttribute(engram_kernel,
                         cudaFuncAttributeMaxDynamicSharedMemorySize, (int)smem);

    dim3 grid(T / TILE, B);
    engram_kernel<<<grid, 320, smem>>>(emb, hid, Wv, bv, Wk, bk,
                                       n1w, n2w, cnw, cvw, out, T);
}

// round 16
// speedup vs baseline: 1.3001x; 1.0014x over previous
#include <cuda_runtime.h>

#define EPSF 1.1920929e-07f
typedef unsigned long long ull;

constexpr int TILE  = 64;
constexpr int HALO  = 10;
constexpr int NROWS = 80;          // token rows (5 x m16 tiles)
constexpr int NGATE = 74;          // TILE + HALO
constexpr int NITEM = NGATE * 4;   // 296 (tok,g) items
constexpr int VSTR  = 36;
constexpr int PSTRW = 68;          // SM_P per-token stride (bank spread)
constexpr int HSTRW = 36;          // SM_HH per-token stride

// shared layout (32-bit word offsets)
constexpr int SM_EHI = 0;                      // [10][32][4] frag-ordered emb hi
constexpr int SM_ELO = SM_EHI + 1280;          // [10][32][4] emb lo
constexpr int SM_V   = SM_ELO + 1280;          // [80][36] f32 values
constexpr int SM_G   = SM_V + NROWS * VSTR;    // [74][4][2] (grr, gate)
constexpr int SM_P   = SM_G + NGATE * 8;       // [80][68] (skk,skh) float2 x8x4
constexpr int SM_HH  = SM_P + NROWS * PSTRW;   // [80][36] shh partials
constexpr int SM_VV  = SM_HH + NROWS * HSTRW;  // [80][8]  svv partials
constexpr int SM_FLOATS = SM_VV + NROWS * 8;   // 14992 words = 59968 B

__device__ __forceinline__ ull fma2(ull a, ull b, ull c) {
    ull d; asm("fma.rn.f32x2 %0, %1, %2, %3;" : "=l"(d) : "l"(a), "l"(b), "l"(c)); return d;
}
__device__ __forceinline__ ull mul2(ull a, ull b) {
    ull d; asm("mul.rn.f32x2 %0, %1, %2;" : "=l"(d) : "l"(a), "l"(b)); return d;
}
__device__ __forceinline__ ull add2(ull a, ull b) {
    ull d; asm("add.rn.f32x2 %0, %1, %2;" : "=l"(d) : "l"(a), "l"(b)); return d;
}
__device__ __forceinline__ ull pack2(float x, float y) {
    ull r; asm("mov.b64 %0, {%1, %2};" : "=l"(r) : "f"(x), "f"(y)); return r;
}
__device__ __forceinline__ float lo2(ull a) { float2 f = *(float2*)&a; return f.x; }
__device__ __forceinline__ float hi2(ull a) { float2 f = *(float2*)&a; return f.y; }
__device__ __forceinline__ float fsqrta(float x) {
    float r; asm("sqrt.approx.f32 %0, %1;" : "=f"(r) : "f"(x)); return r;
}
__device__ __forceinline__ float tanha(float x) {
    float r; asm("tanh.approx.f32 %0, %1;" : "=f"(r) : "f"(x)); return r;
}

__device__ __forceinline__ void split_bf16x2(float x0, float x1,
                                             unsigned& uh, unsigned& ul) {
    unsigned h;
    asm("cvt.rn.bf16x2.f32 %0, %1, %2;" : "=r"(h) : "f"(x1), "f"(x0));
    float h0 = __uint_as_float(h << 16);
    float h1 = __uint_as_float(h & 0xffff0000u);
    float l0 = x0 - h0, l1 = x1 - h1;
    asm("cvt.rn.bf16x2.f32 %0, %1, %2;" : "=r"(ul) : "f"(l1), "f"(l0));
    uh = h;
}

__device__ __forceinline__ void mma16(float* d, unsigned a0, unsigned a1,
                                      unsigned a2, unsigned a3,
                                      unsigned b0, unsigned b1) {
    asm volatile("mma.sync.aligned.m16n8k16.row.col.f32.bf16.bf16.f32 "
                 "{%0,%1,%2,%3}, {%4,%5,%6,%7}, {%8,%9}, {%0,%1,%2,%3};"
                 : "+f"(d[0]), "+f"(d[1]), "+f"(d[2]), "+f"(d[3])
                 : "r"(a0), "r"(a1), "r"(a2), "r"(a3), "r"(b0), "r"(b1));
}

__global__ void __launch_bounds__(320, 3)
engram_kernel(const float* __restrict__ emb, const float* __restrict__ hid,
              const float* __restrict__ Wv,  const float* __restrict__ bv,
              const float* __restrict__ Wk,  const float* __restrict__ bk,
              const float* __restrict__ n1w, const float* __restrict__ n2w,
              const float* __restrict__ cnw, const float* __restrict__ cvw,
              float* __restrict__ out, int T)
{
    extern __shared__ float sm[];
    unsigned* ehi = (unsigned*)(sm + SM_EHI);
    unsigned* elo = (unsigned*)(sm + SM_ELO);

    const int tid        = threadIdx.x;
    const int b          = blockIdx.y;
    const int tile_start = blockIdx.x * TILE;
    const long base_tok  = (long)b * T + tile_start;
    const float* hbase   = hid + (base_tok - HALO) * 128;

    const int w  = tid >> 5, l = tid & 31;
    const int lr = l >> 2, lc = l & 3;

    // ---- L2 prefetch of this block's hid rows (consumed in Phase A) ----
    if (tid < NGATE * 4) {
        const int row = tid >> 2, line = tid & 3;
        if (tile_start - HALO + row >= 0)
            asm volatile("prefetch.global.L2 [%0];"
                         :: "l"(hbase + row * 128 + line * 32));
    }

    // ---- per-thread B fragments + bias from weights ----
    unsigned H[8], L[8];
#pragma unroll
    for (int i = 0; i < 8; i++) {
        const int j = i >> 2, kb = (i >> 1) & 1, idx = i & 1;
        const int row = w * 16 + j * 8 + lr;
        const int t   = kb * 8 + lc + idx * 4;
        const float* src = (row < 128) ? (Wk + row * 32) : (Wv + (row - 128) * 32);
        float2 p = *(const float2*)(src + 2 * t);
        split_bf16x2(p.x, p.y, H[i], L[i]);
    }
    float4 bf;
    {
        const int n0 = w * 16, n1 = w * 16 + 8;
        const float* b0 = (n0 < 128) ? (bk + n0) : (bv + n0 - 128);
        const float* b1 = (n1 < 128) ? (bk + n1) : (bv + n1 - 128);
        bf = make_float4(b0[2 * lc], b0[2 * lc + 1], b1[2 * lc], b1[2 * lc + 1]);
    }
    // nn pairs for this thread's key columns (warps 0-7 only use these)
    ull NN0 = 0, NN8 = 0;
    if (w < 8) {
        const int chb2 = w * 16 + 2 * lc;
        float2 a1 = *(const float2*)(n1w + chb2);
        float2 a2 = *(const float2*)(n2w + chb2);
        float2 b1 = *(const float2*)(n1w + chb2 + 8);
        float2 b2 = *(const float2*)(n2w + chb2 + 8);
        NN0 = pack2(a1.x * a2.x, a1.y * a2.y);
        NN8 = pack2(b1.x * b2.x, b1.y * b2.y);
    }

    // ---- stage emb (hi/lo bf16x2) in MMA-fragment order ----
    for (int i4 = tid; i4 < NROWS * 8; i4 += 320) {
        int tok = i4 >> 3, q = i4 & 7;
        int gt  = tile_start - HALO + tok;
        float4 val = make_float4(0.f, 0.f, 0.f, 0.f);
        if (tok < NGATE && gt >= 0)
            val = ((const float4*)emb)[(base_tok - HALO + tok) * 8 + q];
        unsigned h0, l0, h1, l1;
        split_bf16x2(val.x, val.y, h0, l0);
        split_bf16x2(val.z, val.w, h1, l1);
        const int m = tok >> 4, r = tok & 15;
        const int half = r >> 3, plr = r & 7;
        const int p = 2 * q;
        const int kb = p >> 3, idx = (p >> 2) & 1, plc = p & 3;
        const int addr = (m * 2 + kb) * 128 + (plr * 4 + plc) * 4 + half + 2 * idx;
        ehi[addr] = h0; elo[addr] = l0;
        ehi[addr + 4] = h1; elo[addr + 4] = l1;
    }
    __syncthreads();

    // ---- Phase A: MMA + in-register norm partials ----
#pragma unroll 1
    for (int m = 0; m < 5; m++) {
        const int t0 = m * 16;
        const int tk1 = t0 + lr, tk2 = tk1 + 8;

        // h loads for this thread's (row, col) fragment positions (warps 0-7)
        float2 h1a = make_float2(0.f, 0.f), h1b = h1a, h2a = h1a, h2b = h1a;
        if (w < 8) {
            const int coff = w * 16 + 2 * lc;
            const float* hp1 = hbase + tk1 * 128 + coff;
            const float* hp2 = hbase + tk2 * 128 + coff;
            if (tk1 < NGATE && tile_start - HALO + tk1 >= 0) {
                h1a = *(const float2*)hp1;
                h1b = *(const float2*)(hp1 + 8);
            }
            if (tk2 < NGATE && tile_start - HALO + tk2 >= 0) {
                h2a = *(const float2*)hp2;
                h2b = *(const float2*)(hp2 + 8);
            }
        }

        float d0[4], d1[4];
        d0[0] = bf.x; d0[1] = bf.y; d0[2] = bf.x; d0[3] = bf.y;
        d1[0] = bf.z; d1[1] = bf.w; d1[2] = bf.z; d1[3] = bf.w;
#pragma unroll
        for (int kb = 0; kb < 2; kb++) {
            const int fb = (m * 2 + kb) * 128 + l * 4;
            uint4 A = *(const uint4*)(ehi + fb);
            uint4 Q = *(const uint4*)(elo + fb);
            mma16(d0, Q.x, Q.y, Q.z, Q.w, H[kb*2],   H[kb*2+1]);   // Al*Bh
            mma16(d1, Q.x, Q.y, Q.z, Q.w, H[4+kb*2], H[4+kb*2+1]);
            mma16(d0, A.x, A.y, A.z, A.w, L[kb*2],   L[kb*2+1]);   // Ah*Bl
            mma16(d1, A.x, A.y, A.z, A.w, L[4+kb*2], L[4+kb*2+1]);
            mma16(d0, A.x, A.y, A.z, A.w, H[kb*2],   H[kb*2+1]);   // Ah*Bh
            mma16(d1, A.x, A.y, A.z, A.w, H[4+kb*2], H[4+kb*2+1]);
        }

        ull D1a = pack2(d0[0], d0[1]), D1b = pack2(d1[0], d1[1]);
        ull D2a = pack2(d0[2], d0[3]), D2b = pack2(d1[2], d1[3]);

        if (w < 8) {   // key channels: skk/skh/shh partials
            ull H1a = pack2(h1a.x, h1a.y), H1b = pack2(h1b.x, h1b.y);
            ull H2a = pack2(h2a.x, h2a.y), H2b = pack2(h2b.x, h2b.y);
            ull HN1a = mul2(H1a, NN0), HN1b = mul2(H1b, NN8);
            ull HN2a = mul2(H2a, NN0), HN2b = mul2(H2b, NN8);

            ull skk1 = fma2(D1b, D1b, mul2(D1a, D1a));
            ull skh1 = fma2(D1b, HN1b, mul2(D1a, HN1a));
            ull shh1 = fma2(H1b, H1b, mul2(H1a, H1a));
            ull skk2 = fma2(D2b, D2b, mul2(D2a, D2a));
            ull skh2 = fma2(D2b, HN2b, mul2(D2a, HN2a));
            ull shh2 = fma2(H2b, H2b, mul2(H2a, H2a));

            *(float2*)(sm + SM_P + tk1 * PSTRW + w * 8 + lc * 2) =
                make_float2(lo2(skk1) + hi2(skk1), lo2(skh1) + hi2(skh1));
            *(float2*)(sm + SM_P + tk2 * PSTRW + w * 8 + lc * 2) =
                make_float2(lo2(skk2) + hi2(skk2), lo2(skh2) + hi2(skh2));
            sm[SM_HH + tk1 * HSTRW + w * 4 + lc] = lo2(shh1) + hi2(shh1);
            sm[SM_HH + tk2 * HSTRW + w * 4 + lc] = lo2(shh2) + hi2(shh2);
        } else {       // value channels: V stores + svv partials
            float* vd = sm + SM_V + (w - 8) * 16 + 2 * lc;
            *(float2*)(vd + tk1 * VSTR)     = *(float2*)&D1a;
            *(float2*)(vd + tk2 * VSTR)     = *(float2*)&D2a;
            *(float2*)(vd + 8 + tk1 * VSTR) = *(float2*)&D1b;
            *(float2*)(vd + 8 + tk2 * VSTR) = *(float2*)&D2b;
            ull svv1 = fma2(D1b, D1b, mul2(D1a, D1a));
            ull svv2 = fma2(D2b, D2b, mul2(D2a, D2a));
            sm[SM_VV + tk1 * 8 + (w - 8) * 4 + lc] = lo2(svv1) + hi2(svv1);
            sm[SM_VV + tk2 * 8 + (w - 8) * 4 + lc] = lo2(svv2) + hi2(svv2);
        }
    }
    __syncthreads();

    // ---- Phase B: tiny — combine partials, compute gate/grr ----
    if (tid < NITEM) {
        const int tok = tid >> 2, g = tid & 3;
        float grr = 0.f, gate = 0.f;
        if (tile_start - HALO + tok >= 0) {
            const ulonglong2* pk = (const ulonglong2*)(sm + SM_P + tok * PSTRW + g * 16);
            ulonglong2 a = pk[0], b2 = pk[1], c2 = pk[2], d2 = pk[3];
            ull s = add2(add2(add2(a.x, a.y), add2(b2.x, b2.y)),
                         add2(add2(c2.x, c2.y), add2(d2.x, d2.y)));
            const ulonglong2* ph = (const ulonglong2*)(sm + SM_HH + tok * HSTRW + g * 8);
            ulonglong2 hh0 = ph[0], hh1 = ph[1];
            ull sh2 = add2(add2(hh0.x, hh0.y), add2(hh1.x, hh1.y));
            const ulonglong2* pv = (const ulonglong2*)(sm + SM_VV + tok * 8);
            ulonglong2 vv0 = pv[0], vv1 = pv[1];
            ull sv2 = add2(add2(vv0.x, vv0.y), add2(vv1.x, vv1.y));

            const float skk = lo2(s), skh = hi2(s);
            const float shh = lo2(sh2) + hi2(sh2);
            const float svv = lo2(sv2) + hi2(sv2);
            const float rs1 = rsqrtf(skk * (1.f/32.f) + EPSF);
            const float rs2 = rsqrtf(shh * (1.f/32.f) + EPSF);
            const float dot = skh * rs1 * rs2 * 0.17677669529663687f;
            const float sq  = fsqrta(fmaxf(fabsf(dot), 1e-6f));
            const float gs  = (dot > 0.f) ? sq : ((dot < 0.f) ? -sq : 0.f);
            gate = fmaf(0.5f, tanha(0.5f * gs), 0.5f);   // sigmoid(gs)
            grr  = gate * rsqrtf(gate * gate * svv * (1.f/32.f) + EPSF);
        }
        sm[SM_G + tok * 8 + g * 2 + 0] = grr;
        sm[SM_G + tok * 8 + g * 2 + 1] = gate;
    }
    __syncthreads();

    // ---- Phase C: conv + tanh-SiLU + residual ----
    {
        const int g    = l >> 3;
        const int c0   = (l & 7) * 4;
        const int chb  = g * 32 + c0;
        float4 cw0 = ((const float4*)cvw)[chb + 0];
        float4 cw1 = ((const float4*)cvw)[chb + 1];
        float4 cw2 = ((const float4*)cvw)[chb + 2];
        float4 cw3 = ((const float4*)cvw)[chb + 3];
        ull t9a = pack2(cw0.x, cw1.x), t9b = pack2(cw2.x, cw3.x);
        ull t6a = pack2(cw0.y, cw1.y), t6b = pack2(cw2.y, cw3.y);
        ull t3a = pack2(cw0.z, cw1.z), t3b = pack2(cw2.z, cw3.z);
        ull t0a = pack2(cw0.w, cw1.w), t0b = pack2(cw2.w, cw3.w);
        ull cna = pack2(cnw[chb], cnw[chb+1]), cnb = pack2(cnw[chb+2], cnw[chb+3]);
        const ull HALF2 = pack2(0.5f, 0.5f);

        for (int mt = w; mt < TILE; mt += 10) {
            const int tok = mt + HALO;
            const float* gp = sm + SM_G;
            const float grr9 = gp[(tok-9)*8 + g*2], grr6 = gp[(tok-6)*8 + g*2];
            const float grr3 = gp[(tok-3)*8 + g*2];
            const float2 g0g = *(const float2*)(gp + tok*8 + g*2);  // (grr0, gate)
            const float grr0 = g0g.x, gate = g0g.y;
            const ulonglong2 v9 = *(const ulonglong2*)&sm[SM_V + (tok-9)*VSTR + c0];
            const ulonglong2 v6 = *(const ulonglong2*)&sm[SM_V + (tok-6)*VSTR + c0];
            const ulonglong2 v3 = *(const ulonglong2*)&sm[SM_V + (tok-3)*VSTR + c0];
            const ulonglong2 v0 = *(const ulonglong2*)&sm[SM_V + (tok  )*VSTR + c0];
            const ull g92 = pack2(grr9, grr9), g62 = pack2(grr6, grr6);
            const ull g32 = pack2(grr3, grr3), g02 = pack2(grr0, grr0);
            ull ya = mul2(mul2(t9a, v9.x), g92);
            ull yb = mul2(mul2(t9b, v9.y), g92);
            ya = fma2(mul2(t6a, v6.x), g62, ya);
            yb = fma2(mul2(t6b, v6.y), g62, yb);
            ya = fma2(mul2(t3a, v3.x), g32, ya);
            yb = fma2(mul2(t3b, v3.y), g32, yb);
            ya = fma2(mul2(t0a, v0.x), g02, ya);
            yb = fma2(mul2(t0b, v0.y), g02, yb);
            ya = mul2(ya, cna);
            yb = mul2(yb, cnb);
            ull hya = mul2(ya, HALF2);
            ull hyb = mul2(yb, HALF2);
            ull ta = pack2(tanha(lo2(hya)), tanha(hi2(hya)));
            ull tb = pack2(tanha(lo2(hyb)), tanha(hi2(hyb)));
            ull sa = fma2(hya, ta, hya);
            ull sb = fma2(hyb, tb, hyb);
            float4 o;
            o.x = fmaf(gate, lo2(v0.x), lo2(sa));
            o.y = fmaf(gate, hi2(v0.x), hi2(sa));
            o.z = fmaf(gate, lo2(v0.y), lo2(sb));
            o.w = fmaf(gate, hi2(v0.y), hi2(sb));
            ((float4*)out)[(((base_tok + mt) * 4 + g) * 32 + c0) >> 2] = o;
        }
    }
}

extern "C" void kernel_launch(void* const* d_in, const int* in_sizes, int n_in,
                              void* d_out, int out_size)
{
    const float* emb = (const float*)d_in[0];
    const float* hid = (const float*)d_in[1];
    const float* Wv  = (const float*)d_in[2];
    const float* bv  = (const float*)d_in[3];
    const float* Wk  = (const float*)d_in[4];
    const float* bk  = (const float*)d_in[5];
    const float* n1w = (const float*)d_in[6];
    const float* n2w = (const float*)d_in[7];
    const float* cnw = (const float*)d_in[8];
    const float* cvw = (const float*)d_in[9];
    float* out = (float*)d_out;

    const int T = 8192;
    const int B = in_sizes[0] / (T * 32);
    const size_t smem = SM_FLOATS * sizeof(float);   // 59968 B

    cudaFuncSetAttribute(engram_kernel,
                         cudaFuncAttributeMaxDynamicSharedMemorySize, (int)smem);

    dim3 grid(T / TILE, B);
    engram_kernel<<<grid, 320, smem>>>(emb, hid, Wv, bv, Wk, bk,
                                       n1w, n2w, cnw, cvw, out, T);
}

// round 17
// speedup vs baseline: 1.3065x; 1.0049x over previous
#include <cuda_runtime.h>

#define EPSF 1.1920929e-07f
typedef unsigned long long ull;

constexpr int TILE  = 64;
constexpr int HALO  = 10;
constexpr int NROWS = 80;          // token rows (5 x m16 tiles)
constexpr int NGATE = 74;          // TILE + HALO
constexpr int NITEM = NGATE * 4;   // 296 (tok,g) items
constexpr int VSTR  = 36;
constexpr int PSTRW = 68;          // SM_P per-token stride (bank spread)
constexpr int HSTRW = 36;          // SM_HH per-token stride

// shared layout (32-bit word offsets)
constexpr int SM_EHI = 0;                      // [10][32][4] frag-ordered emb hi
constexpr int SM_ELO = SM_EHI + 1280;          // [10][32][4] emb lo
constexpr int SM_V   = SM_ELO + 1280;          // [80][36] f32 values
constexpr int SM_G   = SM_V + NROWS * VSTR;    // [74][4][2] (grr, gate)
constexpr int SM_P   = SM_G + NGATE * 8;       // [80][68] (skk,skh) float2 x8x4
constexpr int SM_HH  = SM_P + NROWS * PSTRW;   // [80][36] shh partials
constexpr int SM_VV  = SM_HH + NROWS * HSTRW;  // [80][8]  svv partials
constexpr int SM_FLOATS = SM_VV + NROWS * 8;   // 14992 words = 59968 B

__device__ __forceinline__ ull fma2(ull a, ull b, ull c) {
    ull d; asm("fma.rn.f32x2 %0, %1, %2, %3;" : "=l"(d) : "l"(a), "l"(b), "l"(c)); return d;
}
__device__ __forceinline__ ull mul2(ull a, ull b) {
    ull d; asm("mul.rn.f32x2 %0, %1, %2;" : "=l"(d) : "l"(a), "l"(b)); return d;
}
__device__ __forceinline__ ull add2(ull a, ull b) {
    ull d; asm("add.rn.f32x2 %0, %1, %2;" : "=l"(d) : "l"(a), "l"(b)); return d;
}
__device__ __forceinline__ ull pack2(float x, float y) {
    ull r; asm("mov.b64 %0, {%1, %2};" : "=l"(r) : "f"(x), "f"(y)); return r;
}
__device__ __forceinline__ float lo2(ull a) { float2 f = *(float2*)&a; return f.x; }
__device__ __forceinline__ float hi2(ull a) { float2 f = *(float2*)&a; return f.y; }
__device__ __forceinline__ float fsqrta(float x) {
    float r; asm("sqrt.approx.f32 %0, %1;" : "=f"(r) : "f"(x)); return r;
}
__device__ __forceinline__ float tanha(float x) {
    float r; asm("tanh.approx.f32 %0, %1;" : "=f"(r) : "f"(x)); return r;
}

__device__ __forceinline__ void split_bf16x2(float x0, float x1,
                                             unsigned& uh, unsigned& ul) {
    unsigned h;
    asm("cvt.rn.bf16x2.f32 %0, %1, %2;" : "=r"(h) : "f"(x1), "f"(x0));
    float h0 = __uint_as_float(h << 16);
    float h1 = __uint_as_float(h & 0xffff0000u);
    float l0 = x0 - h0, l1 = x1 - h1;
    asm("cvt.rn.bf16x2.f32 %0, %1, %2;" : "=r"(ul) : "f"(l1), "f"(l0));
    uh = h;
}

__device__ __forceinline__ void mma16(float* d, unsigned a0, unsigned a1,
                                      unsigned a2, unsigned a3,
                                      unsigned b0, unsigned b1) {
    asm volatile("mma.sync.aligned.m16n8k16.row.col.f32.bf16.bf16.f32 "
                 "{%0,%1,%2,%3}, {%4,%5,%6,%7}, {%8,%9}, {%0,%1,%2,%3};"
                 : "+f"(d[0]), "+f"(d[1]), "+f"(d[2]), "+f"(d[3])
                 : "r"(a0), "r"(a1), "r"(a2), "r"(a3), "r"(b0), "r"(b1));
}

__global__ void __launch_bounds__(320, 3)
engram_kernel(const float* __restrict__ emb, const float* __restrict__ hid,
              const float* __restrict__ Wv,  const float* __restrict__ bv,
              const float* __restrict__ Wk,  const float* __restrict__ bk,
              const float* __restrict__ n1w, const float* __restrict__ n2w,
              const float* __restrict__ cnw, const float* __restrict__ cvw,
              float* __restrict__ out, int T)
{
    extern __shared__ float sm[];
    unsigned* ehi = (unsigned*)(sm + SM_EHI);
    unsigned* elo = (unsigned*)(sm + SM_ELO);

    const int tid        = threadIdx.x;
    const int b          = blockIdx.y;
    const int tile_start = blockIdx.x * TILE;
    const long base_tok  = (long)b * T + tile_start;
    const float* hbase   = hid + (base_tok - HALO) * 128;

    const int w  = tid >> 5, l = tid & 31;
    const int lr = l >> 2, lc = l & 3;

    // ---- per-thread B fragments + bias from weights ----
    unsigned H[8], L[8];
#pragma unroll
    for (int i = 0; i < 8; i++) {
        const int j = i >> 2, kb = (i >> 1) & 1, idx = i & 1;
        const int row = w * 16 + j * 8 + lr;
        const int t   = kb * 8 + lc + idx * 4;
        const float* src = (row < 128) ? (Wk + row * 32) : (Wv + (row - 128) * 32);
        float2 p = *(const float2*)(src + 2 * t);
        split_bf16x2(p.x, p.y, H[i], L[i]);
    }
    float4 bf;
    {
        const int n0 = w * 16, n1 = w * 16 + 8;
        const float* b0 = (n0 < 128) ? (bk + n0) : (bv + n0 - 128);
        const float* b1 = (n1 < 128) ? (bk + n1) : (bv + n1 - 128);
        bf = make_float4(b0[2 * lc], b0[2 * lc + 1], b1[2 * lc], b1[2 * lc + 1]);
    }
    // nn pairs for this thread's key columns (warps 0-7 only use these)
    ull NN0 = 0, NN8 = 0;
    if (w < 8) {
        const int chb2 = w * 16 + 2 * lc;
        float2 a1 = *(const float2*)(n1w + chb2);
        float2 a2 = *(const float2*)(n2w + chb2);
        float2 b1 = *(const float2*)(n1w + chb2 + 8);
        float2 b2 = *(const float2*)(n2w + chb2 + 8);
        NN0 = pack2(a1.x * a2.x, a1.y * a2.y);
        NN8 = pack2(b1.x * b2.x, b1.y * b2.y);
    }

    // ---- stage emb (hi/lo bf16x2) in MMA-fragment order ----
    for (int i4 = tid; i4 < NROWS * 8; i4 += 320) {
        int tok = i4 >> 3, q = i4 & 7;
        int gt  = tile_start - HALO + tok;
        float4 val = make_float4(0.f, 0.f, 0.f, 0.f);
        if (tok < NGATE && gt >= 0)
            val = ((const float4*)emb)[(base_tok - HALO + tok) * 8 + q];
        unsigned h0, l0, h1, l1;
        split_bf16x2(val.x, val.y, h0, l0);
        split_bf16x2(val.z, val.w, h1, l1);
        const int m = tok >> 4, r = tok & 15;
        const int half = r >> 3, plr = r & 7;
        const int p = 2 * q;
        const int kb = p >> 3, idx = (p >> 2) & 1, plc = p & 3;
        const int addr = (m * 2 + kb) * 128 + (plr * 4 + plc) * 4 + half + 2 * idx;
        ehi[addr] = h0; elo[addr] = l0;
        ehi[addr + 4] = h1; elo[addr + 4] = l1;
    }
    __syncthreads();

    // ---- Phase A: MMA + in-register norm partials (2 m-tiles in flight) ----
#pragma unroll 2
    for (int m = 0; m < 5; m++) {
        const int t0 = m * 16;
        const int tk1 = t0 + lr, tk2 = tk1 + 8;

        // h loads for this thread's (row, col) fragment positions (warps 0-7)
        float2 h1a = make_float2(0.f, 0.f), h1b = h1a, h2a = h1a, h2b = h1a;
        if (w < 8) {
            const int coff = w * 16 + 2 * lc;
            const float* hp1 = hbase + tk1 * 128 + coff;
            const float* hp2 = hbase + tk2 * 128 + coff;
            if (tk1 < NGATE && tile_start - HALO + tk1 >= 0) {
                h1a = *(const float2*)hp1;
                h1b = *(const float2*)(hp1 + 8);
            }
            if (tk2 < NGATE && tile_start - HALO + tk2 >= 0) {
                h2a = *(const float2*)hp2;
                h2b = *(const float2*)(hp2 + 8);
            }
        }

        float d0[4], d1[4];
        d0[0] = bf.x; d0[1] = bf.y; d0[2] = bf.x; d0[3] = bf.y;
        d1[0] = bf.z; d1[1] = bf.w; d1[2] = bf.z; d1[3] = bf.w;
#pragma unroll
        for (int kb = 0; kb < 2; kb++) {
            const int fb = (m * 2 + kb) * 128 + l * 4;
            uint4 A = *(const uint4*)(ehi + fb);
            uint4 Q = *(const uint4*)(elo + fb);
            mma16(d0, Q.x, Q.y, Q.z, Q.w, H[kb*2],   H[kb*2+1]);   // Al*Bh
            mma16(d1, Q.x, Q.y, Q.z, Q.w, H[4+kb*2], H[4+kb*2+1]);
            mma16(d0, A.x, A.y, A.z, A.w, L[kb*2],   L[kb*2+1]);   // Ah*Bl
            mma16(d1, A.x, A.y, A.z, A.w, L[4+kb*2], L[4+kb*2+1]);
            mma16(d0, A.x, A.y, A.z, A.w, H[kb*2],   H[kb*2+1]);   // Ah*Bh
            mma16(d1, A.x, A.y, A.z, A.w, H[4+kb*2], H[4+kb*2+1]);
        }

        ull D1a = pack2(d0[0], d0[1]), D1b = pack2(d1[0], d1[1]);
        ull D2a = pack2(d0[2], d0[3]), D2b = pack2(d1[2], d1[3]);

        if (w < 8) {   // key channels: skk/skh/shh partials
            ull H1a = pack2(h1a.x, h1a.y), H1b = pack2(h1b.x, h1b.y);
            ull H2a = pack2(h2a.x, h2a.y), H2b = pack2(h2b.x, h2b.y);
            ull HN1a = mul2(H1a, NN0), HN1b = mul2(H1b, NN8);
            ull HN2a = mul2(H2a, NN0), HN2b = mul2(H2b, NN8);

            ull skk1 = fma2(D1b, D1b, mul2(D1a, D1a));
            ull skh1 = fma2(D1b, HN1b, mul2(D1a, HN1a));
            ull shh1 = fma2(H1b, H1b, mul2(H1a, H1a));
            ull skk2 = fma2(D2b, D2b, mul2(D2a, D2a));
            ull skh2 = fma2(D2b, HN2b, mul2(D2a, HN2a));
            ull shh2 = fma2(H2b, H2b, mul2(H2a, H2a));

            *(float2*)(sm + SM_P + tk1 * PSTRW + w * 8 + lc * 2) =
                make_float2(lo2(skk1) + hi2(skk1), lo2(skh1) + hi2(skh1));
            *(float2*)(sm + SM_P + tk2 * PSTRW + w * 8 + lc * 2) =
                make_float2(lo2(skk2) + hi2(skk2), lo2(skh2) + hi2(skh2));
            sm[SM_HH + tk1 * HSTRW + w * 4 + lc] = lo2(shh1) + hi2(shh1);
            sm[SM_HH + tk2 * HSTRW + w * 4 + lc] = lo2(shh2) + hi2(shh2);
        } else {       // value channels: V stores + svv partials
            float* vd = sm + SM_V + (w - 8) * 16 + 2 * lc;
            *(float2*)(vd + tk1 * VSTR)     = *(float2*)&D1a;
            *(float2*)(vd + tk2 * VSTR)     = *(float2*)&D2a;
            *(float2*)(vd + 8 + tk1 * VSTR) = *(float2*)&D1b;
            *(float2*)(vd + 8 + tk2 * VSTR) = *(float2*)&D2b;
            ull svv1 = fma2(D1b, D1b, mul2(D1a, D1a));
            ull svv2 = fma2(D2b, D2b, mul2(D2a, D2a));
            sm[SM_VV + tk1 * 8 + (w - 8) * 4 + lc] = lo2(svv1) + hi2(svv1);
            sm[SM_VV + tk2 * 8 + (w - 8) * 4 + lc] = lo2(svv2) + hi2(svv2);
        }
    }
    __syncthreads();

    // ---- Phase B: tiny — combine partials, compute gate/grr ----
    if (tid < NITEM) {
        const int tok = tid >> 2, g = tid & 3;
        float grr = 0.f, gate = 0.f;
        if (tile_start - HALO + tok >= 0) {
            const ulonglong2* pk = (const ulonglong2*)(sm + SM_P + tok * PSTRW + g * 16);
            ulonglong2 a = pk[0], b2 = pk[1], c2 = pk[2], d2 = pk[3];
            ull s = add2(add2(add2(a.x, a.y), add2(b2.x, b2.y)),
                         add2(add2(c2.x, c2.y), add2(d2.x, d2.y)));
            const ulonglong2* ph = (const ulonglong2*)(sm + SM_HH + tok * HSTRW + g * 8);
            ulonglong2 hh0 = ph[0], hh1 = ph[1];
            ull sh2 = add2(add2(hh0.x, hh0.y), add2(hh1.x, hh1.y));
            const ulonglong2* pv = (const ulonglong2*)(sm + SM_VV + tok * 8);
            ulonglong2 vv0 = pv[0], vv1 = pv[1];
            ull sv2 = add2(add2(vv0.x, vv0.y), add2(vv1.x, vv1.y));

            const float skk = lo2(s), skh = hi2(s);
            const float shh = lo2(sh2) + hi2(sh2);
            const float svv = lo2(sv2) + hi2(sv2);
            const float rs1 = rsqrtf(skk * (1.f/32.f) + EPSF);
            const float rs2 = rsqrtf(shh * (1.f/32.f) + EPSF);
            const float dot = skh * rs1 * rs2 * 0.17677669529663687f;
            const float sq  = fsqrta(fmaxf(fabsf(dot), 1e-6f));
            const float gs  = (dot > 0.f) ? sq : ((dot < 0.f) ? -sq : 0.f);
            gate = fmaf(0.5f, tanha(0.5f * gs), 0.5f);   // sigmoid(gs)
            grr  = gate * rsqrtf(gate * gate * svv * (1.f/32.f) + EPSF);
        }
        sm[SM_G + tok * 8 + g * 2 + 0] = grr;
        sm[SM_G + tok * 8 + g * 2 + 1] = gate;
    }
    __syncthreads();

    // ---- Phase C: conv + tanh-SiLU + residual ----
    {
        const int g    = l >> 3;
        const int c0   = (l & 7) * 4;
        const int chb  = g * 32 + c0;
        float4 cw0 = ((const float4*)cvw)[chb + 0];
        float4 cw1 = ((const float4*)cvw)[chb + 1];
        float4 cw2 = ((const float4*)cvw)[chb + 2];
        float4 cw3 = ((const float4*)cvw)[chb + 3];
        ull t9a = pack2(cw0.x, cw1.x), t9b = pack2(cw2.x, cw3.x);
        ull t6a = pack2(cw0.y, cw1.y), t6b = pack2(cw2.y, cw3.y);
        ull t3a = pack2(cw0.z, cw1.z), t3b = pack2(cw2.z, cw3.z);
        ull t0a = pack2(cw0.w, cw1.w), t0b = pack2(cw2.w, cw3.w);
        ull cna = pack2(cnw[chb], cnw[chb+1]), cnb = pack2(cnw[chb+2], cnw[chb+3]);
        const ull HALF2 = pack2(0.5f, 0.5f);

        for (int mt = w; mt < TILE; mt += 10) {
            const int tok = mt + HALO;
            const float* gp = sm + SM_G;
            const float grr9 = gp[(tok-9)*8 + g*2], grr6 = gp[(tok-6)*8 + g*2];
            const float grr3 = gp[(tok-3)*8 + g*2];
            const float2 g0g = *(const float2*)(gp + tok*8 + g*2);  // (grr0, gate)
            const float grr0 = g0g.x, gate = g0g.y;
            const ulonglong2 v9 = *(const ulonglong2*)&sm[SM_V + (tok-9)*VSTR + c0];
            const ulonglong2 v6 = *(const ulonglong2*)&sm[SM_V + (tok-6)*VSTR + c0];
            const ulonglong2 v3 = *(const ulonglong2*)&sm[SM_V + (tok-3)*VSTR + c0];
            const ulonglong2 v0 = *(const ulonglong2*)&sm[SM_V + (tok  )*VSTR + c0];
            const ull g92 = pack2(grr9, grr9), g62 = pack2(grr6, grr6);
            const ull g32 = pack2(grr3, grr3), g02 = pack2(grr0, grr0);
            ull ya = mul2(mul2(t9a, v9.x), g92);
            ull yb = mul2(mul2(t9b, v9.y), g92);
            ya = fma2(mul2(t6a, v6.x), g62, ya);
            yb = fma2(mul2(t6b, v6.y), g62, yb);
            ya = fma2(mul2(t3a, v3.x), g32, ya);
            yb = fma2(mul2(t3b, v3.y), g32, yb);
            ya = fma2(mul2(t0a, v0.x), g02, ya);
            yb = fma2(mul2(t0b, v0.y), g02, yb);
            ya = mul2(ya, cna);
            yb = mul2(yb, cnb);
            ull hya = mul2(ya, HALF2);
            ull hyb = mul2(yb, HALF2);
            ull ta = pack2(tanha(lo2(hya)), tanha(hi2(hya)));
            ull tb = pack2(tanha(lo2(hyb)), tanha(hi2(hyb)));
            ull sa = fma2(hya, ta, hya);
            ull sb = fma2(hyb, tb, hyb);
            float4 o;
            o.x = fmaf(gate, lo2(v0.x), lo2(sa));
            o.y = fmaf(gate, hi2(v0.x), hi2(sa));
            o.z = fmaf(gate, lo2(v0.y), lo2(sb));
            o.w = fmaf(gate, hi2(v0.y), hi2(sb));
            ((float4*)out)[(((base_tok + mt) * 4 + g) * 32 + c0) >> 2] = o;
        }
    }
}

extern "C" void kernel_launch(void* const* d_in, const int* in_sizes, int n_in,
                              void* d_out, int out_size)
{
    const float* emb = (const float*)d_in[0];
    const float* hid = (const float*)d_in[1];
    const float* Wv  = (const float*)d_in[2];
    const float* bv  = (const float*)d_in[3];
    const float* Wk  = (const float*)d_in[4];
    const float* bk  = (const float*)d_in[5];
    const float* n1w = (const float*)d_in[6];
    const float* n2w = (const float*)d_in[7];
    const float* cnw = (const float*)d_in[8];
    const float* cvw = (const float*)d_in[9];
    float* out = (float*)d_out;

    const int T = 8192;
    const int B = in_sizes[0] / (T * 32);
    const size_t smem = SM_FLOATS * sizeof(float);   // 59968 B

    cudaFuncSetAttribute(engram_kernel,
                         cudaFuncAttributeMaxDynamicSharedMemorySize, (int)smem);

    dim3 grid(T / TILE, B);
    engram_kernel<<<grid, 320, smem>>>(emb, hid, Wv, bv, Wk, bk,
                                       n1w, n2w, cnw, cvw, out, T);
}